// round 1
// baseline (speedup 1.0000x reference)
#include <cuda_runtime.h>
#include <cuda_bf16.h>
#include <cstdint>

// Problem constants
#define Bsz 64
#define Nn  4096
#define Ee  8192
#define Dd  256
#define Hh  256
#define Mm  64

#define MROWS (Bsz * Nn)        // 262144
#define PCOLS 768               // [W1top(256) | W1bot(256) | A1top(128) | A1bot(128)]
#define KDIM  256
#define NEDGE (Bsz * Ee)        // 524288

// Scratch (allocation-free rule: __device__ globals)
__device__ float g_P[(size_t)MROWS * PCOLS];       // 805 MB per-node partials
__device__ float g_Wcat[KDIM * PCOLS];             // 768 KB fused weight matrix

// ---------------------------------------------------------------------------
// Prep: build Wcat[256][768] from W1[512][256] and A1[512][128]
// ---------------------------------------------------------------------------
__global__ void prep_w_kernel(const float* __restrict__ W1, const float* __restrict__ A1) {
    int i = blockIdx.x * blockDim.x + threadIdx.x;
    if (i >= KDIM * PCOLS) return;
    int k = i / PCOLS;
    int c = i % PCOLS;
    float v;
    if (c < 256)        v = W1[k * 256 + c];                 // W1 top half
    else if (c < 512)   v = W1[(256 + k) * 256 + (c - 256)]; // W1 bottom half
    else if (c < 640)   v = A1[k * 128 + (c - 512)];         // A1 top half
    else                v = A1[(256 + k) * 128 + (c - 640)]; // A1 bottom half
    g_Wcat[i] = v;
}

// ---------------------------------------------------------------------------
// SGEMM: g_P[262144, 768] = node_emb[262144, 256] @ g_Wcat[256, 768]
// 128x128 tile, BK=8, 256 threads, 8x8 per-thread micro-tile, fp32.
// ---------------------------------------------------------------------------
__global__ __launch_bounds__(256) void sgemm_kernel(const float* __restrict__ A) {
    __shared__ float As[8][128];
    __shared__ float Bs[8][128];

    const int tid  = threadIdx.x;
    const int brow = blockIdx.x;            // 0..2047  (M tiles)
    const int bcol = blockIdx.y;            // 0..5     (N tiles)

    const float* Ablk = A + (size_t)brow * 128 * KDIM;
    const float* Bblk = g_Wcat + bcol * 128;

    // load indices
    const int arow  = tid >> 1;             // 0..127
    const int acol4 = (tid & 1) * 4;        // 0 or 4
    const int brw   = tid >> 5;             // 0..7
    const int bcl4  = (tid & 31) * 4;       // 0..124

    // micro-tile position
    const int trow = (tid >> 4) * 8;
    const int tcol = (tid & 15) * 8;

    float acc[8][8];
    #pragma unroll
    for (int i = 0; i < 8; i++)
        #pragma unroll
        for (int j = 0; j < 8; j++) acc[i][j] = 0.0f;

    for (int bk = 0; bk < KDIM; bk += 8) {
        float4 av = *reinterpret_cast<const float4*>(Ablk + (size_t)arow * KDIM + bk + acol4);
        As[acol4 + 0][arow] = av.x;
        As[acol4 + 1][arow] = av.y;
        As[acol4 + 2][arow] = av.z;
        As[acol4 + 3][arow] = av.w;
        float4 bv = *reinterpret_cast<const float4*>(Bblk + (size_t)(bk + brw) * PCOLS + bcl4);
        *reinterpret_cast<float4*>(&Bs[brw][bcl4]) = bv;
        __syncthreads();

        #pragma unroll
        for (int k = 0; k < 8; k++) {
            float4 a0 = *reinterpret_cast<const float4*>(&As[k][trow]);
            float4 a1 = *reinterpret_cast<const float4*>(&As[k][trow + 4]);
            float4 b0 = *reinterpret_cast<const float4*>(&Bs[k][tcol]);
            float4 b1 = *reinterpret_cast<const float4*>(&Bs[k][tcol + 4]);
            float ar[8] = {a0.x, a0.y, a0.z, a0.w, a1.x, a1.y, a1.z, a1.w};
            float br[8] = {b0.x, b0.y, b0.z, b0.w, b1.x, b1.y, b1.z, b1.w};
            #pragma unroll
            for (int i = 0; i < 8; i++)
                #pragma unroll
                for (int j = 0; j < 8; j++)
                    acc[i][j] += ar[i] * br[j];
        }
        __syncthreads();
    }

    float* Cb = g_P + ((size_t)brow * 128) * PCOLS + bcol * 128;
    #pragma unroll
    for (int i = 0; i < 8; i++) {
        #pragma unroll
        for (int j = 0; j < 8; j += 4) {
            float4 v = make_float4(acc[i][j], acc[i][j + 1], acc[i][j + 2], acc[i][j + 3]);
            *reinterpret_cast<float4*>(Cb + (size_t)(trow + i) * PCOLS + tcol + j) = v;
        }
    }
}

// ---------------------------------------------------------------------------
// Edge kernel: per-edge scoring + masking.
// 128 threads/block, 8 edges/block. A2 cached in smem.
// ---------------------------------------------------------------------------
#define EPB 8

__global__ __launch_bounds__(128) void edge_kernel(
    const float* __restrict__ army, const int* __restrict__ edges,
    const float* __restrict__ b1, const float* __restrict__ W2, const float* __restrict__ b2,
    const float* __restrict__ a1, const float* __restrict__ A2, const float* __restrict__ a2,
    float* __restrict__ out_edge, float* __restrict__ out_army)
{
    __shared__ float A2s[128][65];
    __shared__ float W2s[256];
    __shared__ float b1s[256];
    __shared__ float a1s[128];
    __shared__ float a2s[64];
    __shared__ float g_s[128];
    __shared__ float p_s[128];
    __shared__ float red[4];
    __shared__ int   s_src, s_tgt;
    __shared__ float s_srcA, s_tgtA;

    const int tid = threadIdx.x;

    // Stage weights in shared
    #pragma unroll
    for (int i = tid; i < 128 * 64; i += 128) A2s[i >> 6][i & 63] = A2[i];
    if (tid < 64)  a2s[tid] = a2[tid];
    a1s[tid] = a1[tid];
    b1s[tid] = b1[tid];       b1s[tid + 128] = b1[tid + 128];
    W2s[tid] = W2[tid];       W2s[tid + 128] = W2[tid + 128];
    const float b2v = b2[0];
    __syncthreads();

    for (int e = 0; e < EPB; e++) {
        const int eidx = blockIdx.x * EPB + e;          // 0..524287
        const int b    = eidx >> 13;                    // /8192

        if (tid == 0) {
            int src = edges[(size_t)eidx * 2];
            int tgt = edges[(size_t)eidx * 2 + 1];
            s_src = src; s_tgt = tgt;
            int sc = min(max(src, 0), Nn - 1);
            int tc = min(max(tgt, 0), Nn - 1);
            s_srcA = army[b * Nn + sc];
            s_tgtA = army[b * Nn + tc];
        }
        __syncthreads();

        const int src = s_src, tgt = s_tgt;
        const int sc = min(max(src, 0), Nn - 1);
        const int tc = min(max(tgt, 0), Nn - 1);
        const float* Ps = g_P + ((size_t)b * Nn + sc) * PCOLS;
        const float* Pt = g_P + ((size_t)b * Nn + tc) * PCOLS;

        // edge-scorer hidden layer + dot with W2 (each thread handles 2 of 256)
        float h0 = Ps[tid]       + Pt[256 + tid]       + b1s[tid];
        float h1 = Ps[tid + 128] + Pt[256 + tid + 128] + b1s[tid + 128];
        h0 = fmaxf(h0, 0.0f);
        h1 = fmaxf(h1, 0.0f);
        float ep = h0 * W2s[tid] + h1 * W2s[tid + 128];
        #pragma unroll
        for (int o = 16; o; o >>= 1) ep += __shfl_xor_sync(0xffffffffu, ep, o);
        if ((tid & 31) == 0) red[tid >> 5] = ep;

        // army-scorer hidden layer (128 units, one per thread)
        float gv = Ps[512 + tid] + Pt[640 + tid] + a1s[tid];
        g_s[tid] = fmaxf(gv, 0.0f);
        __syncthreads();

        // army matvec: g[128] @ A2[128,64]; split j-range over 2 halves
        const int m = tid & 63, half = tid >> 6;
        float acc = 0.0f;
        #pragma unroll
        for (int j = 0; j < 64; j++)
            acc += g_s[half * 64 + j] * A2s[half * 64 + j][m];
        p_s[tid] = acc;
        __syncthreads();

        const float srcA = s_srcA, tgtA = s_tgtA;

        if (tid == 0) {
            float el = red[0] + red[1] + red[2] + red[3] + b2v;
            bool valid = (src >= 0) && (tgt >= 0);
            if (valid && ((srcA <= 2.0f) || (tgtA >= 3.0f * srcA))) el -= 1.0f;
            if (valid && (src == tgt))                              el -= 100.0f;
            out_edge[eidx] = el;
        }
        if (tid < 64) {
            float v = p_s[tid] + p_s[tid + 64] + a2s[tid];
            float maxSend = srcA - 1.0f;
            if (!((float)tid <= maxSend)) v = -1e9f;
            out_army[(size_t)eidx * 64 + tid] = v;
        }
        __syncthreads();   // protect red/g_s/p_s for next edge
    }
}

// ---------------------------------------------------------------------------
// Launch
// ---------------------------------------------------------------------------
extern "C" void kernel_launch(void* const* d_in, const int* in_sizes, int n_in,
                              void* d_out, int out_size) {
    // Resolve inputs by element count (robust to ordering).
    // node:67108864 army:262144 edges:1048576 W1:131072 b1:256 W2:256 b2:1
    // A1:65536 a1:128 A2:8192 a2:64   (b1 precedes W2 in all plausible orders)
    int i_node = -1, i_army = -1, i_edges = -1, i_W1 = -1, i_b1 = -1, i_W2 = -1,
        i_b2 = -1, i_A1 = -1, i_a1 = -1, i_A2 = -1, i_a2 = -1;
    for (int i = 0; i < n_in; i++) {
        switch (in_sizes[i]) {
            case 67108864: i_node = i; break;
            case 262144:   i_army = i; break;
            case 1048576:  i_edges = i; break;
            case 131072:   i_W1 = i; break;
            case 65536:    i_A1 = i; break;
            case 8192:     i_A2 = i; break;
            case 128:      i_a1 = i; break;
            case 64:       i_a2 = i; break;
            case 1:        i_b2 = i; break;
            case 256:      if (i_b1 < 0) i_b1 = i; else i_W2 = i; break;
            default: break;
        }
    }

    const float* node  = (const float*)d_in[i_node];
    const float* army  = (const float*)d_in[i_army];
    const int*   edges = (const int*)  d_in[i_edges];
    const float* W1    = (const float*)d_in[i_W1];
    const float* b1    = (const float*)d_in[i_b1];
    const float* W2    = (const float*)d_in[i_W2];
    const float* b2    = (const float*)d_in[i_b2];
    const float* A1    = (const float*)d_in[i_A1];
    const float* a1    = (const float*)d_in[i_a1];
    const float* A2    = (const float*)d_in[i_A2];
    const float* a2    = (const float*)d_in[i_a2];

    float* out_edge = (float*)d_out;                  // [B*E]
    float* out_army = (float*)d_out + NEDGE;          // [B*E, M]

    prep_w_kernel<<<(KDIM * PCOLS + 255) / 256, 256>>>(W1, A1);

    dim3 ggrid(MROWS / 128, PCOLS / 128);             // (2048, 6)
    sgemm_kernel<<<ggrid, 256>>>(node);

    edge_kernel<<<NEDGE / EPB, 128>>>(army, edges, b1, W2, b2, a1, A2, a2,
                                      out_edge, out_army);
}

// round 7
// speedup vs baseline: 1.9013x; 1.9013x over previous
#include <cuda_runtime.h>
#include <cuda_bf16.h>
#include <cstdint>

// ---------------- problem constants ----------------
#define Bsz 64
#define Nn  4096
#define Ee  8192
#define MROWS (Bsz * Nn)        // 262144
#define PCOLS 768               // [W1top(256) | W1bot(256) | A1top(128) | A1bot(128)]
#define KDIM  256
#define NEDGE (Bsz * Ee)        // 524288
#define K3   768                // 3 x 256 compensated-K

// ---------------- scratch (__device__ globals; no allocs allowed) ----------
__device__ __align__(16) float         g_P[(size_t)MROWS * PCOLS];   // partials (805 MB)
__device__ __align__(16) __nv_bfloat16 g_Abf[(size_t)MROWS * 512];   // [m][0:256)=hi, [256:512)=lo
__device__ __align__(16) __nv_bfloat16 g_B3[(size_t)PCOLS * K3];     // [n][k3]: [Whi|Wlo|Whi]

// ---------------- helpers ----------------
__device__ __forceinline__ uint32_t smem_u32(const void* p) {
    uint32_t a;
    asm("{ .reg .u64 t; cvta.to.shared.u64 t, %1; cvt.u32.u64 %0, t; }" : "=r"(a) : "l"(p));
    return a;
}
__device__ __forceinline__ void cp16(uint32_t dst, const void* src) {
    asm volatile("cp.async.cg.shared.global [%0], [%1], 16;" :: "r"(dst), "l"(src));
}
#define CP_COMMIT() asm volatile("cp.async.commit_group;" ::: "memory")
#define CP_WAIT(n)  asm volatile("cp.async.wait_group %0;" :: "n"(n) : "memory")

__device__ __forceinline__ void mma_bf16(float* c,
    uint32_t a0, uint32_t a1, uint32_t a2, uint32_t a3, uint32_t b0, uint32_t b1) {
    asm volatile(
        "mma.sync.aligned.m16n8k16.row.col.f32.bf16.bf16.f32 "
        "{%0,%1,%2,%3}, {%4,%5,%6,%7}, {%8,%9}, {%0,%1,%2,%3};"
        : "+f"(c[0]), "+f"(c[1]), "+f"(c[2]), "+f"(c[3])
        : "r"(a0), "r"(a1), "r"(a2), "r"(a3), "r"(b0), "r"(b1));
}

// ---------------------------------------------------------------------------
// prep_a: split node embeddings into bf16 hi/lo.  g_Abf[m][k]=hi, [m][256+k]=lo
// ---------------------------------------------------------------------------
__global__ __launch_bounds__(256) void prep_a_kernel(const float* __restrict__ node) {
    int i = blockIdx.x * blockDim.x + threadIdx.x;      // 0 .. 16777215
    if (i >= MROWS * 64) return;
    int m  = i >> 6;
    int kq = (i & 63) * 4;
    float4 v = *reinterpret_cast<const float4*>(node + (size_t)m * 256 + kq);
    __nv_bfloat16 h[4], l[4];
    float vv[4] = {v.x, v.y, v.z, v.w};
    #pragma unroll
    for (int j = 0; j < 4; j++) {
        h[j] = __float2bfloat16_rn(vv[j]);
        l[j] = __float2bfloat16_rn(vv[j] - __bfloat162float(h[j]));
    }
    *reinterpret_cast<uint2*>(&g_Abf[(size_t)m * 512 + kq])       = *reinterpret_cast<uint2*>(h);
    *reinterpret_cast<uint2*>(&g_Abf[(size_t)m * 512 + 256 + kq]) = *reinterpret_cast<uint2*>(l);
}

// ---------------------------------------------------------------------------
// prep_w: g_B3[n][k3] (k-major) = [Whi | Wlo | Whi] of Wcat[k][n]
// ---------------------------------------------------------------------------
__global__ __launch_bounds__(256) void prep_w_kernel(const float* __restrict__ W1,
                                                     const float* __restrict__ A1) {
    int i = blockIdx.x * blockDim.x + threadIdx.x;
    if (i >= PCOLS * K3) return;
    int n  = i / K3;
    int k3 = i % K3;
    int seg = k3 >> 8;             // 0:hi 1:lo 2:hi
    int k   = k3 & 255;
    float v;
    if (n < 256)        v = W1[k * 256 + n];
    else if (n < 512)   v = W1[(256 + k) * 256 + (n - 256)];
    else if (n < 640)   v = A1[k * 128 + (n - 512)];
    else                v = A1[(256 + k) * 128 + (n - 640)];
    __nv_bfloat16 hi = __float2bfloat16_rn(v);
    g_B3[i] = (seg == 1) ? __float2bfloat16_rn(v - __bfloat162float(hi)) : hi;
}

// ---------------------------------------------------------------------------
// GEMM: g_P[262144,768] = A3[262144,768k] @ B3[768k,768]  (bf16 mma.sync, f32 acc)
// CTA tile 128M x 128N, BK=32, 24 k-iters, cp.async double buffer.
// ---------------------------------------------------------------------------
#define BK 32
#define AST 40   // smem stride in halves (80 B: 16B-aligned, conflict-free)

__global__ __launch_bounds__(256) void gemm_kernel() {
    __shared__ __align__(16) __nv_bfloat16 As[2][128][AST];
    __shared__ __align__(16) __nv_bfloat16 Bs[2][128][AST];

    const int tid  = threadIdx.x;
    const int wid  = tid >> 5, lane = tid & 31;
    const int g    = lane >> 2, tig = lane & 3;
    const int warp_m = (wid >> 2) * 64;      // 0 / 64
    const int warp_n = (wid & 3) * 32;       // 0,32,64,96
    const int n0 = blockIdx.x * 128;         // 0..640
    const int m0 = blockIdx.y * 128;

    const uint32_t sAs = smem_u32(&As[0][0][0]);
    const uint32_t sBs = smem_u32(&Bs[0][0][0]);

    float acc[4][4][4];
    #pragma unroll
    for (int i = 0; i < 4; i++)
        #pragma unroll
        for (int j = 0; j < 4; j++)
            #pragma unroll
            for (int q = 0; q < 4; q++) acc[i][j][q] = 0.0f;

    // stage loader: A rows from g_Abf (seg-dependent k base), B rows from g_B3
    auto load_stage = [&](int ks, int buf) {
        const int seg  = ks >> 3;
        const int a_k0 = ((seg == 2) ? 256 : 0) + (ks & 7) * BK;
        const int b_k0 = ks * BK;
        const uint32_t da = sAs + (uint32_t)buf * (128 * AST * 2);
        const uint32_t db = sBs + (uint32_t)buf * (128 * AST * 2);
        #pragma unroll
        for (int h = 0; h < 2; h++) {
            int id = tid + h * 256;          // 0..511
            int r  = id >> 2, p = id & 3;
            cp16(da + (uint32_t)(r * AST + p * 8) * 2,
                 &g_Abf[(size_t)(m0 + r) * 512 + a_k0 + p * 8]);
            cp16(db + (uint32_t)(r * AST + p * 8) * 2,
                 &g_B3[(size_t)(n0 + r) * K3 + b_k0 + p * 8]);
        }
    };

    load_stage(0, 0);
    CP_COMMIT();

    for (int ks = 0; ks < 24; ks++) {
        if (ks + 1 < 24) {
            load_stage(ks + 1, (ks + 1) & 1);
            CP_COMMIT();
            CP_WAIT(1);
        } else {
            CP_WAIT(0);
        }
        __syncthreads();

        const uint32_t* As32 = reinterpret_cast<const uint32_t*>(&As[ks & 1][0][0]);
        const uint32_t* Bs32 = reinterpret_cast<const uint32_t*>(&Bs[ks & 1][0][0]);

        #pragma unroll
        for (int ksel = 0; ksel < 2; ksel++) {
            // FRAGMENT BASE FIX: 16 bf16 k-elements = 16 halves = 8 u32 per fragment.
            // (was ksel*4 -> k 8..23 reread, k 24..31 dropped -> rel_err 0.256)
            uint32_t a[4][4], b[4][2];
            #pragma unroll
            for (int mi = 0; mi < 4; mi++) {
                int row = warp_m + mi * 16 + g;
                int w0  = row * (AST / 2) + ksel * 8 + tig;
                a[mi][0] = As32[w0];
                a[mi][1] = As32[w0 + 8 * (AST / 2)];
                a[mi][2] = As32[w0 + 4];
                a[mi][3] = As32[w0 + 4 + 8 * (AST / 2)];
            }
            #pragma unroll
            for (int nj = 0; nj < 4; nj++) {
                int n  = warp_n + nj * 8 + g;
                int w0 = n * (AST / 2) + ksel * 8 + tig;
                b[nj][0] = Bs32[w0];
                b[nj][1] = Bs32[w0 + 4];
            }
            #pragma unroll
            for (int mi = 0; mi < 4; mi++)
                #pragma unroll
                for (int nj = 0; nj < 4; nj++)
                    mma_bf16(acc[mi][nj], a[mi][0], a[mi][1], a[mi][2], a[mi][3],
                             b[nj][0], b[nj][1]);
        }
        __syncthreads();
    }

    // epilogue: c0,c1 -> (row g, col 2tig..+1); c2,c3 -> (row g+8, same cols)
    #pragma unroll
    for (int mi = 0; mi < 4; mi++) {
        #pragma unroll
        for (int nj = 0; nj < 4; nj++) {
            int row = m0 + warp_m + mi * 16 + g;
            int col = n0 + warp_n + nj * 8 + 2 * tig;
            *reinterpret_cast<float2*>(&g_P[(size_t)row * PCOLS + col]) =
                make_float2(acc[mi][nj][0], acc[mi][nj][1]);
            *reinterpret_cast<float2*>(&g_P[(size_t)(row + 8) * PCOLS + col]) =
                make_float2(acc[mi][nj][2], acc[mi][nj][3]);
        }
    }
}

// ---------------------------------------------------------------------------
// Edge kernel: one warp per edge. 256 thr/block, 8 warps, grid-stride.
// ---------------------------------------------------------------------------
#define EDGE_BLOCKS 2048
#define EDGE_WARPS  (EDGE_BLOCKS * 8)

__global__ __launch_bounds__(256) void edge_kernel(
    const float* __restrict__ army, const int* __restrict__ edges,
    const float* __restrict__ b1, const float* __restrict__ W2, const float* __restrict__ b2,
    const float* __restrict__ a1, const float* __restrict__ A2, const float* __restrict__ a2,
    float* __restrict__ out_edge, float* __restrict__ out_army)
{
    __shared__ float2 A2s2[128 * 33];     // [j][m/2], pad stride 33
    __shared__ float4 g_s4[8 * 32];       // per-warp g (128 floats as 32 float4)
    __shared__ float  b1s[256], W2s[256], a1s[128];
    __shared__ float2 a2s2[32];

    const int tid = threadIdx.x, w = tid >> 5, lane = tid & 31;

    for (int i = tid; i < 128 * 32; i += 256) {
        int j = i >> 5, m2 = i & 31;
        A2s2[j * 33 + m2] = make_float2(A2[j * 64 + m2 * 2], A2[j * 64 + m2 * 2 + 1]);
    }
    b1s[tid] = b1[tid];
    W2s[tid] = W2[tid];
    if (tid < 128) a1s[tid] = a1[tid];
    if (tid < 32)  a2s2[tid] = make_float2(a2[tid * 2], a2[tid * 2 + 1]);
    const float b2v = b2[0];
    __syncthreads();

    for (int e = blockIdx.x * 8 + w; e < NEDGE; e += EDGE_WARPS) {
        const int b = e >> 13;
        const int src = edges[2 * e], tgt = edges[2 * e + 1];
        const int sc = min(max(src, 0), Nn - 1);
        const int tc = min(max(tgt, 0), Nn - 1);
        const float* Ps = g_P + ((size_t)(b << 12) + sc) * PCOLS;
        const float* Pt = g_P + ((size_t)(b << 12) + tc) * PCOLS;

        // edge scorer: h[256] -> dot W2
        float ep = 0.0f;
        #pragma unroll
        for (int q = 0; q < 2; q++) {
            int f = lane + 32 * q;
            float4 ps = *reinterpret_cast<const float4*>(Ps + 4 * f);
            float4 pt = *reinterpret_cast<const float4*>(Pt + 256 + 4 * f);
            float4 bb = *reinterpret_cast<const float4*>(b1s + 4 * f);
            float4 ww = *reinterpret_cast<const float4*>(W2s + 4 * f);
            ep += fmaxf(ps.x + pt.x + bb.x, 0.0f) * ww.x;
            ep += fmaxf(ps.y + pt.y + bb.y, 0.0f) * ww.y;
            ep += fmaxf(ps.z + pt.z + bb.z, 0.0f) * ww.z;
            ep += fmaxf(ps.w + pt.w + bb.w, 0.0f) * ww.w;
        }
        #pragma unroll
        for (int o = 16; o; o >>= 1) ep += __shfl_xor_sync(0xffffffffu, ep, o);

        // army scorer hidden: g[128]
        {
            float4 ps = *reinterpret_cast<const float4*>(Ps + 512 + 4 * lane);
            float4 pt = *reinterpret_cast<const float4*>(Pt + 640 + 4 * lane);
            float4 aa = *reinterpret_cast<const float4*>(a1s + 4 * lane);
            float4 g4;
            g4.x = fmaxf(ps.x + pt.x + aa.x, 0.0f);
            g4.y = fmaxf(ps.y + pt.y + aa.y, 0.0f);
            g4.z = fmaxf(ps.z + pt.z + aa.z, 0.0f);
            g4.w = fmaxf(ps.w + pt.w + aa.w, 0.0f);
            g_s4[w * 32 + lane] = g4;
        }
        __syncwarp();

        // matvec: out m = 2*lane, 2*lane+1
        float acc0 = 0.0f, acc1 = 0.0f;
        #pragma unroll
        for (int j4 = 0; j4 < 32; j4++) {
            float4 gg = g_s4[w * 32 + j4];
            float2 r0 = A2s2[(4 * j4 + 0) * 33 + lane];
            float2 r1 = A2s2[(4 * j4 + 1) * 33 + lane];
            float2 r2 = A2s2[(4 * j4 + 2) * 33 + lane];
            float2 r3 = A2s2[(4 * j4 + 3) * 33 + lane];
            acc0 += gg.x * r0.x; acc1 += gg.x * r0.y;
            acc0 += gg.y * r1.x; acc1 += gg.y * r1.y;
            acc0 += gg.z * r2.x; acc1 += gg.z * r2.y;
            acc0 += gg.w * r3.x; acc1 += gg.w * r3.y;
        }

        const float srcA = army[(b << 12) + sc];
        const float tgtA = army[(b << 12) + tc];

        if (lane == 0) {
            float el = ep + b2v;
            bool valid = (src >= 0) && (tgt >= 0);
            if (valid && ((srcA <= 2.0f) || (tgtA >= 3.0f * srcA))) el -= 1.0f;
            if (valid && (src == tgt))                              el -= 100.0f;
            out_edge[e] = el;
        }
        const float maxS = srcA - 1.0f;
        float2 a2v = a2s2[lane];
        float v0 = ((float)(2 * lane)     <= maxS) ? acc0 + a2v.x : -1e9f;
        float v1 = ((float)(2 * lane + 1) <= maxS) ? acc1 + a2v.y : -1e9f;
        *reinterpret_cast<float2*>(out_army + (size_t)e * 64 + 2 * lane) = make_float2(v0, v1);
        __syncwarp();    // protect g_s4 reuse
    }
}

// ---------------------------------------------------------------------------
// Launch
// ---------------------------------------------------------------------------
extern "C" void kernel_launch(void* const* d_in, const int* in_sizes, int n_in,
                              void* d_out, int out_size) {
    int i_node = -1, i_army = -1, i_edges = -1, i_W1 = -1, i_b1 = -1, i_W2 = -1,
        i_b2 = -1, i_A1 = -1, i_a1 = -1, i_A2 = -1, i_a2 = -1;
    for (int i = 0; i < n_in; i++) {
        switch (in_sizes[i]) {
            case 67108864: i_node = i; break;
            case 262144:   i_army = i; break;
            case 1048576:  i_edges = i; break;
            case 131072:   i_W1 = i; break;
            case 65536:    i_A1 = i; break;
            case 8192:     i_A2 = i; break;
            case 128:      i_a1 = i; break;
            case 64:       i_a2 = i; break;
            case 1:        i_b2 = i; break;
            case 256:      if (i_b1 < 0) i_b1 = i; else i_W2 = i; break;
            default: break;
        }
    }

    const float* node  = (const float*)d_in[i_node];
    const float* army  = (const float*)d_in[i_army];
    const int*   edges = (const int*)  d_in[i_edges];

    float* out_edge = (float*)d_out;
    float* out_army = (float*)d_out + NEDGE;

    prep_a_kernel<<<(MROWS * 64 + 255) / 256, 256>>>(node);
    prep_w_kernel<<<(PCOLS * K3 + 255) / 256, 256>>>((const float*)d_in[i_W1],
                                                     (const float*)d_in[i_A1]);

    dim3 ggrid(PCOLS / 128, MROWS / 128);            // (6, 2048): col fastest
    gemm_kernel<<<ggrid, 256>>>();

    edge_kernel<<<EDGE_BLOCKS, 256>>>(army, edges,
                                      (const float*)d_in[i_b1], (const float*)d_in[i_W2],
                                      (const float*)d_in[i_b2], (const float*)d_in[i_a1],
                                      (const float*)d_in[i_A2], (const float*)d_in[i_a2],
                                      out_edge, out_army);
}

// round 8
// speedup vs baseline: 1.9955x; 1.0495x over previous
#include <cuda_runtime.h>
#include <cuda_bf16.h>
#include <cstdint>

// ---------------- problem constants ----------------
#define Bsz 64
#define Nn  4096
#define Ee  8192
#define MROWS (Bsz * Nn)        // 262144
#define PCOLS 768               // [W1top(256) | W1bot(256) | A1top(128) | A1bot(128)]
#define KDIM  256
#define NEDGE (Bsz * Ee)        // 524288
#define K3   768                // 3 x 256 compensated-K

// ---------------- scratch (__device__ globals; no allocs allowed) ----------
__device__ __align__(16) float         g_P[(size_t)MROWS * PCOLS];   // partials (805 MB)
__device__ __align__(16) __nv_bfloat16 g_Abf[(size_t)MROWS * 512];   // [m][0:256)=hi, [256:512)=lo
__device__ __align__(16) __nv_bfloat16 g_B3[(size_t)PCOLS * K3];     // [n][k3]: [Whi|Wlo|Whi]
__device__ __align__(16) uint32_t      g_A2Th[64 * 64];              // A2^T hi, [n][k/2] u32-packed
__device__ __align__(16) uint32_t      g_A2Tl[64 * 64];              // A2^T lo

// ---------------- helpers ----------------
__device__ __forceinline__ uint32_t smem_u32(const void* p) {
    uint32_t a;
    asm("{ .reg .u64 t; cvta.to.shared.u64 t, %1; cvt.u32.u64 %0, t; }" : "=r"(a) : "l"(p));
    return a;
}
__device__ __forceinline__ void cp16(uint32_t dst, const void* src) {
    asm volatile("cp.async.cg.shared.global [%0], [%1], 16;" :: "r"(dst), "l"(src));
}
#define CP_COMMIT() asm volatile("cp.async.commit_group;" ::: "memory")
#define CP_WAIT(n)  asm volatile("cp.async.wait_group %0;" :: "n"(n) : "memory")

__device__ __forceinline__ void mma_bf16(float* c,
    uint32_t a0, uint32_t a1, uint32_t a2, uint32_t a3, uint32_t b0, uint32_t b1) {
    asm volatile(
        "mma.sync.aligned.m16n8k16.row.col.f32.bf16.bf16.f32 "
        "{%0,%1,%2,%3}, {%4,%5,%6,%7}, {%8,%9}, {%0,%1,%2,%3};"
        : "+f"(c[0]), "+f"(c[1]), "+f"(c[2]), "+f"(c[3])
        : "r"(a0), "r"(a1), "r"(a2), "r"(a3), "r"(b0), "r"(b1));
}
__device__ __forceinline__ uint32_t pack_bf16(float lo, float hi) {
    __nv_bfloat162 t = __floats2bfloat162_rn(lo, hi);
    return *reinterpret_cast<uint32_t*>(&t);
}

// ---------------------------------------------------------------------------
// prep_a: split node embeddings into bf16 hi/lo.  g_Abf[m][k]=hi, [m][256+k]=lo
// ---------------------------------------------------------------------------
__global__ __launch_bounds__(256) void prep_a_kernel(const float* __restrict__ node) {
    int i = blockIdx.x * blockDim.x + threadIdx.x;      // 0 .. 16777215
    if (i >= MROWS * 64) return;
    int m  = i >> 6;
    int kq = (i & 63) * 4;
    float4 v = *reinterpret_cast<const float4*>(node + (size_t)m * 256 + kq);
    __nv_bfloat16 h[4], l[4];
    float vv[4] = {v.x, v.y, v.z, v.w};
    #pragma unroll
    for (int j = 0; j < 4; j++) {
        h[j] = __float2bfloat16_rn(vv[j]);
        l[j] = __float2bfloat16_rn(vv[j] - __bfloat162float(h[j]));
    }
    *reinterpret_cast<uint2*>(&g_Abf[(size_t)m * 512 + kq])       = *reinterpret_cast<uint2*>(h);
    *reinterpret_cast<uint2*>(&g_Abf[(size_t)m * 512 + 256 + kq]) = *reinterpret_cast<uint2*>(l);
}

// ---------------------------------------------------------------------------
// prep_w: g_B3[n][k3] (k-major) = [Whi | Wlo | Whi] of Wcat[k][n]
// ---------------------------------------------------------------------------
__global__ __launch_bounds__(256) void prep_w_kernel(const float* __restrict__ W1,
                                                     const float* __restrict__ A1) {
    int i = blockIdx.x * blockDim.x + threadIdx.x;
    if (i >= PCOLS * K3) return;
    int n  = i / K3;
    int k3 = i % K3;
    int seg = k3 >> 8;             // 0:hi 1:lo 2:hi
    int k   = k3 & 255;
    float v;
    if (n < 256)        v = W1[k * 256 + n];
    else if (n < 512)   v = W1[(256 + k) * 256 + (n - 256)];
    else if (n < 640)   v = A1[k * 128 + (n - 512)];
    else                v = A1[(256 + k) * 128 + (n - 640)];
    __nv_bfloat16 hi = __float2bfloat16_rn(v);
    g_B3[i] = (seg == 1) ? __float2bfloat16_rn(v - __bfloat162float(hi)) : hi;
}

// ---------------------------------------------------------------------------
// prep_a2: A2^T hi/lo as u32-packed fragments.  g_A2Th[n][kk] = (bf16(A2[2kk][n]),
// bf16(A2[2kk+1][n])) packed; lo likewise.
// ---------------------------------------------------------------------------
__global__ __launch_bounds__(256) void prep_a2_kernel(const float* __restrict__ A2) {
    int i = blockIdx.x * blockDim.x + threadIdx.x;   // 0..4095
    if (i >= 64 * 64) return;
    int n  = i >> 6;
    int kk = i & 63;
    float v0 = A2[(2 * kk)     * 64 + n];
    float v1 = A2[(2 * kk + 1) * 64 + n];
    float h0 = __bfloat162float(__float2bfloat16_rn(v0));
    float h1 = __bfloat162float(__float2bfloat16_rn(v1));
    g_A2Th[i] = pack_bf16(h0, h1);
    g_A2Tl[i] = pack_bf16(v0 - h0, v1 - h1);
}

// ---------------------------------------------------------------------------
// GEMM: g_P[262144,768] = A3[262144,768k] @ B3[768k,768]  (bf16 mma.sync, f32 acc)
// CTA tile 128M x 128N, BK=32, 24 k-iters, cp.async double buffer.
// ---------------------------------------------------------------------------
#define BK 32
#define AST 40   // smem stride in halves (80 B: 16B-aligned, conflict-free)

__global__ __launch_bounds__(256) void gemm_kernel() {
    __shared__ __align__(16) __nv_bfloat16 As[2][128][AST];
    __shared__ __align__(16) __nv_bfloat16 Bs[2][128][AST];

    const int tid  = threadIdx.x;
    const int wid  = tid >> 5, lane = tid & 31;
    const int g    = lane >> 2, tig = lane & 3;
    const int warp_m = (wid >> 2) * 64;      // 0 / 64
    const int warp_n = (wid & 3) * 32;       // 0,32,64,96
    const int n0 = blockIdx.x * 128;         // 0..640
    const int m0 = blockIdx.y * 128;

    const uint32_t sAs = smem_u32(&As[0][0][0]);
    const uint32_t sBs = smem_u32(&Bs[0][0][0]);

    float acc[4][4][4];
    #pragma unroll
    for (int i = 0; i < 4; i++)
        #pragma unroll
        for (int j = 0; j < 4; j++)
            #pragma unroll
            for (int q = 0; q < 4; q++) acc[i][j][q] = 0.0f;

    auto load_stage = [&](int ks, int buf) {
        const int seg  = ks >> 3;
        const int a_k0 = ((seg == 2) ? 256 : 0) + (ks & 7) * BK;
        const int b_k0 = ks * BK;
        const uint32_t da = sAs + (uint32_t)buf * (128 * AST * 2);
        const uint32_t db = sBs + (uint32_t)buf * (128 * AST * 2);
        #pragma unroll
        for (int h = 0; h < 2; h++) {
            int id = tid + h * 256;          // 0..511
            int r  = id >> 2, p = id & 3;
            cp16(da + (uint32_t)(r * AST + p * 8) * 2,
                 &g_Abf[(size_t)(m0 + r) * 512 + a_k0 + p * 8]);
            cp16(db + (uint32_t)(r * AST + p * 8) * 2,
                 &g_B3[(size_t)(n0 + r) * K3 + b_k0 + p * 8]);
        }
    };

    load_stage(0, 0);
    CP_COMMIT();

    for (int ks = 0; ks < 24; ks++) {
        if (ks + 1 < 24) {
            load_stage(ks + 1, (ks + 1) & 1);
            CP_COMMIT();
            CP_WAIT(1);
        } else {
            CP_WAIT(0);
        }
        __syncthreads();

        const uint32_t* As32 = reinterpret_cast<const uint32_t*>(&As[ks & 1][0][0]);
        const uint32_t* Bs32 = reinterpret_cast<const uint32_t*>(&Bs[ks & 1][0][0]);

        #pragma unroll
        for (int ksel = 0; ksel < 2; ksel++) {
            uint32_t a[4][4], b[4][2];
            #pragma unroll
            for (int mi = 0; mi < 4; mi++) {
                int row = warp_m + mi * 16 + g;
                int w0  = row * (AST / 2) + ksel * 8 + tig;
                a[mi][0] = As32[w0];
                a[mi][1] = As32[w0 + 8 * (AST / 2)];
                a[mi][2] = As32[w0 + 4];
                a[mi][3] = As32[w0 + 4 + 8 * (AST / 2)];
            }
            #pragma unroll
            for (int nj = 0; nj < 4; nj++) {
                int n  = warp_n + nj * 8 + g;
                int w0 = n * (AST / 2) + ksel * 8 + tig;
                b[nj][0] = Bs32[w0];
                b[nj][1] = Bs32[w0 + 4];
            }
            #pragma unroll
            for (int mi = 0; mi < 4; mi++)
                #pragma unroll
                for (int nj = 0; nj < 4; nj++)
                    mma_bf16(acc[mi][nj], a[mi][0], a[mi][1], a[mi][2], a[mi][3],
                             b[nj][0], b[nj][1]);
        }
        __syncthreads();
    }

    #pragma unroll
    for (int mi = 0; mi < 4; mi++) {
        #pragma unroll
        for (int nj = 0; nj < 4; nj++) {
            int row = m0 + warp_m + mi * 16 + g;
            int col = n0 + warp_n + nj * 8 + 2 * tig;
            *reinterpret_cast<float2*>(&g_P[(size_t)row * PCOLS + col]) =
                make_float2(acc[mi][nj][0], acc[mi][nj][1]);
            *reinterpret_cast<float2*>(&g_P[(size_t)(row + 8) * PCOLS + col]) =
                make_float2(acc[mi][nj][2], acc[mi][nj][3]);
        }
    }
}

// ---------------------------------------------------------------------------
// Edge kernel v2: warp-batched. Each warp handles 16 edges per tile:
//   phase 1 (per edge): gather P rows, edge-logit dot (warp reduce), compute
//     g[128], split to bf16 hi/lo, stage into swizzled smem.
//   phase 2: 16x64 = [16,128]@[128,64] matvec via m16n8k16 mma, 3-term bf16.
// A2^T hi/lo fragments come from global (L1-resident, 32KB).
// ---------------------------------------------------------------------------
#define EW 4                     // warps per block
#define NTILES (NEDGE / 16)      // 32768
#define EDGE_GRID 4096           // x EW warps -> 2 tiles per warp

__global__ __launch_bounds__(128) void edge_kernel(
    const float* __restrict__ army, const int* __restrict__ edges,
    const float* __restrict__ b1, const float* __restrict__ W2, const float* __restrict__ b2,
    const float* __restrict__ a1, const float* __restrict__ a2,
    float* __restrict__ out_edge, float* __restrict__ out_army)
{
    __shared__ uint32_t stg_h[EW][16 * 64];   // per-warp g hi staging (swizzled)
    __shared__ uint32_t stg_l[EW][16 * 64];   // per-warp g lo staging
    __shared__ float b1s[256], W2s[256], a1s[128];
    __shared__ float srcAs[EW][16];

    const int tid = threadIdx.x, w = tid >> 5, lane = tid & 31;
    const int grp = lane >> 2, tig = lane & 3;

    b1s[tid] = b1[tid];       b1s[tid + 128] = b1[tid + 128];
    W2s[tid] = W2[tid];       W2s[tid + 128] = W2[tid + 128];
    a1s[tid] = a1[tid];
    const float b2v = b2[0];

    float2 a2g[8];
    #pragma unroll
    for (int nj = 0; nj < 8; nj++) {
        int m = nj * 8 + 2 * tig;
        a2g[nj] = make_float2(a2[m], a2[m + 1]);
    }
    __syncthreads();

    for (int tile = blockIdx.x * EW + w; tile < NTILES; tile += EDGE_GRID * EW) {
        const int e0 = tile * 16;

        // ---- phase 1: 16 edges ----
        #pragma unroll 1
        for (int e = 0; e < 16; e++) {
            const int eidx = e0 + e;
            const int b = eidx >> 13;
            const int src = edges[2 * eidx], tgt = edges[2 * eidx + 1];
            const int sc = min(max(src, 0), Nn - 1);
            const int tc = min(max(tgt, 0), Nn - 1);
            const float* Ps = g_P + ((size_t)(b << 12) + sc) * PCOLS;
            const float* Pt = g_P + ((size_t)(b << 12) + tc) * PCOLS;

            // edge scorer: h[256] -> dot W2
            float ep = 0.0f;
            #pragma unroll
            for (int q = 0; q < 2; q++) {
                int f = lane + 32 * q;
                float4 ps = *reinterpret_cast<const float4*>(Ps + 4 * f);
                float4 pt = *reinterpret_cast<const float4*>(Pt + 256 + 4 * f);
                float4 bb = *reinterpret_cast<const float4*>(b1s + 4 * f);
                float4 ww = *reinterpret_cast<const float4*>(W2s + 4 * f);
                ep += fmaxf(ps.x + pt.x + bb.x, 0.0f) * ww.x;
                ep += fmaxf(ps.y + pt.y + bb.y, 0.0f) * ww.y;
                ep += fmaxf(ps.z + pt.z + bb.z, 0.0f) * ww.z;
                ep += fmaxf(ps.w + pt.w + bb.w, 0.0f) * ww.w;
            }
            #pragma unroll
            for (int o = 16; o; o >>= 1) ep += __shfl_xor_sync(0xffffffffu, ep, o);

            // army hidden g[4] per lane, split hi/lo, stage (swizzled)
            {
                float4 ps = *reinterpret_cast<const float4*>(Ps + 512 + 4 * lane);
                float4 pt = *reinterpret_cast<const float4*>(Pt + 640 + 4 * lane);
                float4 aa = *reinterpret_cast<const float4*>(a1s + 4 * lane);
                float g0 = fmaxf(ps.x + pt.x + aa.x, 0.0f);
                float g1 = fmaxf(ps.y + pt.y + aa.y, 0.0f);
                float g2 = fmaxf(ps.z + pt.z + aa.z, 0.0f);
                float g3 = fmaxf(ps.w + pt.w + aa.w, 0.0f);
                float h0 = __bfloat162float(__float2bfloat16_rn(g0));
                float h1 = __bfloat162float(__float2bfloat16_rn(g1));
                float h2 = __bfloat162float(__float2bfloat16_rn(g2));
                float h3 = __bfloat162float(__float2bfloat16_rn(g3));
                const uint32_t sw = 4u * (e & 7);
                const uint32_t o0 = (uint32_t)(e * 64) + ((2u * lane)     ^ sw);
                const uint32_t o1 = (uint32_t)(e * 64) + ((2u * lane + 1) ^ sw);
                stg_h[w][o0] = pack_bf16(h0, h1);
                stg_h[w][o1] = pack_bf16(h2, h3);
                stg_l[w][o0] = pack_bf16(g0 - h0, g1 - h1);
                stg_l[w][o1] = pack_bf16(g2 - h2, g3 - h3);
            }

            const float srcA = army[(b << 12) + sc];
            const float tgtA = army[(b << 12) + tc];
            if (lane == 0) {
                float el = ep + b2v;
                bool valid = (src >= 0) && (tgt >= 0);
                if (valid && ((srcA <= 2.0f) || (tgtA >= 3.0f * srcA))) el -= 1.0f;
                if (valid && (src == tgt))                              el -= 100.0f;
                out_edge[eidx] = el;
                srcAs[w][e] = srcA;
            }
        }
        __syncwarp();

        // ---- phase 2: [16,128] @ [128,64] via mma, 3-term bf16 ----
        float acc[8][4];
        #pragma unroll
        for (int nj = 0; nj < 8; nj++)
            #pragma unroll
            for (int q = 0; q < 4; q++) acc[nj][q] = 0.0f;

        const uint32_t swg = 4u * grp;
        #pragma unroll
        for (int ks = 0; ks < 8; ks++) {
            const uint32_t kb = 8u * ks;
            uint32_t ah0 = stg_h[w][grp * 64       + ((kb + tig)     ^ swg)];
            uint32_t ah1 = stg_h[w][(grp + 8) * 64 + ((kb + tig)     ^ swg)];
            uint32_t ah2 = stg_h[w][grp * 64       + ((kb + 4 + tig) ^ swg)];
            uint32_t ah3 = stg_h[w][(grp + 8) * 64 + ((kb + 4 + tig) ^ swg)];
            uint32_t al0 = stg_l[w][grp * 64       + ((kb + tig)     ^ swg)];
            uint32_t al1 = stg_l[w][(grp + 8) * 64 + ((kb + tig)     ^ swg)];
            uint32_t al2 = stg_l[w][grp * 64       + ((kb + 4 + tig) ^ swg)];
            uint32_t al3 = stg_l[w][(grp + 8) * 64 + ((kb + 4 + tig) ^ swg)];
            #pragma unroll
            for (int nj = 0; nj < 8; nj++) {
                const int bi = (nj * 8 + grp) * 64 + kb + tig;
                uint32_t bh0 = g_A2Th[bi], bh1 = g_A2Th[bi + 4];
                uint32_t bl0 = g_A2Tl[bi], bl1 = g_A2Tl[bi + 4];
                mma_bf16(acc[nj], ah0, ah1, ah2, ah3, bh0, bh1);
                mma_bf16(acc[nj], ah0, ah1, ah2, ah3, bl0, bl1);
                mma_bf16(acc[nj], al0, al1, al2, al3, bh0, bh1);
            }
        }

        // ---- output: rows grp (edge e0+grp) and grp+8 ----
        const float mS0 = srcAs[w][grp] - 1.0f;
        const float mS1 = srcAs[w][grp + 8] - 1.0f;
        float* o0 = out_army + (size_t)(e0 + grp) * 64;
        float* o1 = out_army + (size_t)(e0 + grp + 8) * 64;
        #pragma unroll
        for (int nj = 0; nj < 8; nj++) {
            const int m = nj * 8 + 2 * tig;
            const float fm0 = (float)m, fm1 = (float)(m + 1);
            float v0 = (fm0 <= mS0) ? acc[nj][0] + a2g[nj].x : -1e9f;
            float v1 = (fm1 <= mS0) ? acc[nj][1] + a2g[nj].y : -1e9f;
            float v2 = (fm0 <= mS1) ? acc[nj][2] + a2g[nj].x : -1e9f;
            float v3 = (fm1 <= mS1) ? acc[nj][3] + a2g[nj].y : -1e9f;
            *reinterpret_cast<float2*>(o0 + m) = make_float2(v0, v1);
            *reinterpret_cast<float2*>(o1 + m) = make_float2(v2, v3);
        }
        __syncwarp();   // protect staging reuse next tile
    }
}

// ---------------------------------------------------------------------------
// Launch
// ---------------------------------------------------------------------------
extern "C" void kernel_launch(void* const* d_in, const int* in_sizes, int n_in,
                              void* d_out, int out_size) {
    int i_node = -1, i_army = -1, i_edges = -1, i_W1 = -1, i_b1 = -1, i_W2 = -1,
        i_b2 = -1, i_A1 = -1, i_a1 = -1, i_A2 = -1, i_a2 = -1;
    for (int i = 0; i < n_in; i++) {
        switch (in_sizes[i]) {
            case 67108864: i_node = i; break;
            case 262144:   i_army = i; break;
            case 1048576:  i_edges = i; break;
            case 131072:   i_W1 = i; break;
            case 65536:    i_A1 = i; break;
            case 8192:     i_A2 = i; break;
            case 128:      i_a1 = i; break;
            case 64:       i_a2 = i; break;
            case 1:        i_b2 = i; break;
            case 256:      if (i_b1 < 0) i_b1 = i; else i_W2 = i; break;
            default: break;
        }
    }

    const float* node  = (const float*)d_in[i_node];
    const float* army  = (const float*)d_in[i_army];
    const int*   edges = (const int*)  d_in[i_edges];

    float* out_edge = (float*)d_out;
    float* out_army = (float*)d_out + NEDGE;

    prep_a_kernel<<<(MROWS * 64 + 255) / 256, 256>>>(node);
    prep_w_kernel<<<(PCOLS * K3 + 255) / 256, 256>>>((const float*)d_in[i_W1],
                                                     (const float*)d_in[i_A1]);
    prep_a2_kernel<<<16, 256>>>((const float*)d_in[i_A2]);

    dim3 ggrid(PCOLS / 128, MROWS / 128);            // (6, 2048): col fastest
    gemm_kernel<<<ggrid, 256>>>();

    edge_kernel<<<EDGE_GRID, 128>>>(army, edges,
                                    (const float*)d_in[i_b1], (const float*)d_in[i_W2],
                                    (const float*)d_in[i_b2], (const float*)d_in[i_a1],
                                    (const float*)d_in[i_a2],
                                    out_edge, out_army);
}

// round 9
// speedup vs baseline: 2.4689x; 1.2373x over previous
#include <cuda_runtime.h>
#include <cuda_bf16.h>
#include <cstdint>

// ---------------- problem constants ----------------
#define Bsz 64
#define Nn  4096
#define Ee  8192
#define MROWS (Bsz * Nn)        // 262144
#define PCOLS 768               // [W1top(256) | W1bot(256) | A1top(128) | A1bot(128)]
#define KDIM  256
#define NEDGE (Bsz * Ee)        // 524288
#define K3   768                // 3 x 256 compensated-K

// ---------------- scratch (__device__ globals; no allocs allowed) ----------
__device__ __align__(16) float         g_P[(size_t)MROWS * PCOLS];   // partials (805 MB)
__device__ __align__(16) __nv_bfloat16 g_Abf[(size_t)MROWS * 512];   // [m][0:256)=hi, [256:512)=lo
__device__ __align__(16) __nv_bfloat16 g_B3[(size_t)PCOLS * K3];     // [n][k3]: [Whi|Wlo|Whi]
__device__ __align__(16) uint32_t      g_A2Th[64 * 64];              // A2^T hi, u32-packed pairs
__device__ __align__(16) uint32_t      g_A2Tl[64 * 64];              // A2^T lo

// ---------------- helpers ----------------
__device__ __forceinline__ uint32_t smem_u32(const void* p) {
    uint32_t a;
    asm("{ .reg .u64 t; cvta.to.shared.u64 t, %1; cvt.u32.u64 %0, t; }" : "=r"(a) : "l"(p));
    return a;
}
__device__ __forceinline__ void cp16(uint32_t dst, const void* src) {
    asm volatile("cp.async.cg.shared.global [%0], [%1], 16;" :: "r"(dst), "l"(src));
}
#define CP_COMMIT() asm volatile("cp.async.commit_group;" ::: "memory")
#define CP_WAIT(n)  asm volatile("cp.async.wait_group %0;" :: "n"(n) : "memory")

__device__ __forceinline__ void mma_bf16(float* c,
    uint32_t a0, uint32_t a1, uint32_t a2, uint32_t a3, uint32_t b0, uint32_t b1) {
    asm volatile(
        "mma.sync.aligned.m16n8k16.row.col.f32.bf16.bf16.f32 "
        "{%0,%1,%2,%3}, {%4,%5,%6,%7}, {%8,%9}, {%0,%1,%2,%3};"
        : "+f"(c[0]), "+f"(c[1]), "+f"(c[2]), "+f"(c[3])
        : "r"(a0), "r"(a1), "r"(a2), "r"(a3), "r"(b0), "r"(b1));
}
__device__ __forceinline__ void ldsm_x4(uint32_t* r, uint32_t addr) {
    asm volatile("ldmatrix.sync.aligned.m8n8.x4.shared.b16 {%0,%1,%2,%3}, [%4];"
        : "=r"(r[0]), "=r"(r[1]), "=r"(r[2]), "=r"(r[3]) : "r"(addr));
}
__device__ __forceinline__ void ldsm_x2(uint32_t* r, uint32_t addr) {
    asm volatile("ldmatrix.sync.aligned.m8n8.x2.shared.b16 {%0,%1}, [%2];"
        : "=r"(r[0]), "=r"(r[1]) : "r"(addr));
}
__device__ __forceinline__ uint32_t pack_bf16(float lo, float hi) {
    __nv_bfloat162 t = __floats2bfloat162_rn(lo, hi);
    return *reinterpret_cast<uint32_t*>(&t);
}

// ---------------------------------------------------------------------------
// prep_a: split node embeddings into bf16 hi/lo.
// ---------------------------------------------------------------------------
__global__ __launch_bounds__(256) void prep_a_kernel(const float* __restrict__ node) {
    int i = blockIdx.x * blockDim.x + threadIdx.x;
    if (i >= MROWS * 64) return;
    int m  = i >> 6;
    int kq = (i & 63) * 4;
    float4 v = *reinterpret_cast<const float4*>(node + (size_t)m * 256 + kq);
    __nv_bfloat16 h[4], l[4];
    float vv[4] = {v.x, v.y, v.z, v.w};
    #pragma unroll
    for (int j = 0; j < 4; j++) {
        h[j] = __float2bfloat16_rn(vv[j]);
        l[j] = __float2bfloat16_rn(vv[j] - __bfloat162float(h[j]));
    }
    *reinterpret_cast<uint2*>(&g_Abf[(size_t)m * 512 + kq])       = *reinterpret_cast<uint2*>(h);
    *reinterpret_cast<uint2*>(&g_Abf[(size_t)m * 512 + 256 + kq]) = *reinterpret_cast<uint2*>(l);
}

// ---------------------------------------------------------------------------
// prep_w: g_B3[n][k3] (k-major) = [Whi | Wlo | Whi] of Wcat[k][n]
// ---------------------------------------------------------------------------
__global__ __launch_bounds__(256) void prep_w_kernel(const float* __restrict__ W1,
                                                     const float* __restrict__ A1) {
    int i = blockIdx.x * blockDim.x + threadIdx.x;
    if (i >= PCOLS * K3) return;
    int n  = i / K3;
    int k3 = i % K3;
    int seg = k3 >> 8;             // 0:hi 1:lo 2:hi
    int k   = k3 & 255;
    float v;
    if (n < 256)        v = W1[k * 256 + n];
    else if (n < 512)   v = W1[(256 + k) * 256 + (n - 256)];
    else if (n < 640)   v = A1[k * 128 + (n - 512)];
    else                v = A1[(256 + k) * 128 + (n - 640)];
    __nv_bfloat16 hi = __float2bfloat16_rn(v);
    g_B3[i] = (seg == 1) ? __float2bfloat16_rn(v - __bfloat162float(hi)) : hi;
}

// ---------------------------------------------------------------------------
// prep_a2: A2^T hi/lo u32-packed fragments.
// ---------------------------------------------------------------------------
__global__ __launch_bounds__(256) void prep_a2_kernel(const float* __restrict__ A2) {
    int i = blockIdx.x * blockDim.x + threadIdx.x;
    if (i >= 64 * 64) return;
    int n  = i >> 6;
    int kk = i & 63;
    float v0 = A2[(2 * kk)     * 64 + n];
    float v1 = A2[(2 * kk + 1) * 64 + n];
    float h0 = __bfloat162float(__float2bfloat16_rn(v0));
    float h1 = __bfloat162float(__float2bfloat16_rn(v1));
    g_A2Th[i] = pack_bf16(h0, h1);
    g_A2Tl[i] = pack_bf16(v0 - h0, v1 - h1);
}

// ---------------------------------------------------------------------------
// GEMM: g_P[262144,768] = A3 @ B3 (bf16 mma.sync, f32 acc)
// 128x128 tile, BK=32, 24 iters, 3-stage cp.async pipeline, 1 sync/iter,
// ldmatrix fragment loads, 2 CTAs/SM.
// ---------------------------------------------------------------------------
#define BK 32
#define AST 40                    // smem row stride in halves
#define STG_H (128 * AST)         // halves per array per stage
#define STAGE_B (2 * STG_H * 2)   // bytes per stage (A+B)
#define GEMM_SMEM (3 * STAGE_B)   // 61440

__global__ __launch_bounds__(256, 2) void gemm_kernel() {
    extern __shared__ __align__(16) __nv_bfloat16 dyn[];
    const uint32_t sb = smem_u32(dyn);

    const int tid  = threadIdx.x;
    const int wid  = tid >> 5, lane = tid & 31;
    const int g    = lane >> 2, tig = lane & 3;
    const int warp_m = (wid >> 2) * 64;      // 0 / 64
    const int warp_n = (wid & 3) * 32;       // 0,32,64,96
    const int n0 = blockIdx.x * 128;
    const int m0 = blockIdx.y * 128;

    float acc[4][4][4];
    #pragma unroll
    for (int i = 0; i < 4; i++)
        #pragma unroll
        for (int j = 0; j < 4; j++)
            #pragma unroll
            for (int q = 0; q < 4; q++) acc[i][j][q] = 0.0f;

    auto load_stage = [&](int ks, int buf) {
        const int seg  = ks >> 3;
        const int a_k0 = ((seg == 2) ? 256 : 0) + (ks & 7) * BK;
        const int b_k0 = ks * BK;
        const uint32_t da = sb + (uint32_t)buf * STAGE_B;
        const uint32_t db = da + STG_H * 2;
        #pragma unroll
        for (int h = 0; h < 2; h++) {
            int id = tid + h * 256;
            int r  = id >> 2, p = id & 3;
            cp16(da + (uint32_t)(r * AST + p * 8) * 2,
                 &g_Abf[(size_t)(m0 + r) * 512 + a_k0 + p * 8]);
            cp16(db + (uint32_t)(r * AST + p * 8) * 2,
                 &g_B3[(size_t)(n0 + r) * K3 + b_k0 + p * 8]);
        }
    };

    // per-lane ldmatrix address components
    const int a_row = lane & 15;              // within m16 tile
    const int a_k8  = ((lane >> 4) & 1) * 8;  // k-half group
    const int b_row = lane & 7;               // within n8 tile
    const int b_k8  = ((lane >> 3) & 1) * 8;

    load_stage(0, 0); CP_COMMIT();
    load_stage(1, 1); CP_COMMIT();

    for (int ks = 0; ks < 24; ks++) {
        if (ks < 22) { CP_WAIT(1); } else { CP_WAIT(0); }
        __syncthreads();

        const uint32_t aB = sb + (uint32_t)(ks % 3) * STAGE_B;
        const uint32_t bB = aB + STG_H * 2;

        #pragma unroll
        for (int ksel = 0; ksel < 2; ksel++) {
            uint32_t a[4][4], b[4][2];
            #pragma unroll
            for (int mi = 0; mi < 4; mi++) {
                int row = warp_m + mi * 16 + a_row;
                ldsm_x4(a[mi], aB + (uint32_t)(row * AST + ksel * 16 + a_k8) * 2);
            }
            #pragma unroll
            for (int nj = 0; nj < 4; nj++) {
                int row = warp_n + nj * 8 + b_row;
                ldsm_x2(b[nj], bB + (uint32_t)(row * AST + ksel * 16 + b_k8) * 2);
            }
            #pragma unroll
            for (int mi = 0; mi < 4; mi++)
                #pragma unroll
                for (int nj = 0; nj < 4; nj++)
                    mma_bf16(acc[mi][nj], a[mi][0], a[mi][1], a[mi][2], a[mi][3],
                             b[nj][0], b[nj][1]);
        }

        if (ks + 2 < 24) { load_stage(ks + 2, (ks + 2) % 3); CP_COMMIT(); }
    }

    #pragma unroll
    for (int mi = 0; mi < 4; mi++) {
        #pragma unroll
        for (int nj = 0; nj < 4; nj++) {
            int row = m0 + warp_m + mi * 16 + g;
            int col = n0 + warp_n + nj * 8 + 2 * tig;
            *reinterpret_cast<float2*>(&g_P[(size_t)row * PCOLS + col]) =
                make_float2(acc[mi][nj][0], acc[mi][nj][1]);
            *reinterpret_cast<float2*>(&g_P[(size_t)(row + 8) * PCOLS + col]) =
                make_float2(acc[mi][nj][2], acc[mi][nj][3]);
        }
    }
}

// ---------------------------------------------------------------------------
// Edge kernel: warp-batched (16 edges/tile). Small grid => grid-stride window
// spans ~4.6 batches of g_P (~58MB) => gathers hit L2.
// ---------------------------------------------------------------------------
#define EW 4
#define NTILES (NEDGE / 16)      // 32768
#define EDGE_GRID 592

__global__ __launch_bounds__(128) void edge_kernel(
    const float* __restrict__ army, const int* __restrict__ edges,
    const float* __restrict__ b1, const float* __restrict__ W2, const float* __restrict__ b2,
    const float* __restrict__ a1, const float* __restrict__ a2,
    float* __restrict__ out_edge, float* __restrict__ out_army)
{
    __shared__ uint32_t stg_h[EW][16 * 64];
    __shared__ uint32_t stg_l[EW][16 * 64];
    __shared__ float b1s[256], W2s[256], a1s[128];
    __shared__ float srcAs[EW][16];

    const int tid = threadIdx.x, w = tid >> 5, lane = tid & 31;
    const int grp = lane >> 2, tig = lane & 3;

    b1s[tid] = b1[tid];       b1s[tid + 128] = b1[tid + 128];
    W2s[tid] = W2[tid];       W2s[tid + 128] = W2[tid + 128];
    a1s[tid] = a1[tid];
    const float b2v = b2[0];

    float2 a2g[8];
    #pragma unroll
    for (int nj = 0; nj < 8; nj++) {
        int m = nj * 8 + 2 * tig;
        a2g[nj] = make_float2(a2[m], a2[m + 1]);
    }
    __syncthreads();

    for (int tile = blockIdx.x * EW + w; tile < NTILES; tile += EDGE_GRID * EW) {
        const int e0 = tile * 16;

        // ---- phase 1: 16 edges (unroll 2 => overlap gathers across edges) ----
        #pragma unroll 2
        for (int e = 0; e < 16; e++) {
            const int eidx = e0 + e;
            const int b = eidx >> 13;
            const int src = edges[2 * eidx], tgt = edges[2 * eidx + 1];
            const int sc = min(max(src, 0), Nn - 1);
            const int tc = min(max(tgt, 0), Nn - 1);
            const float* Ps = g_P + ((size_t)(b << 12) + sc) * PCOLS;
            const float* Pt = g_P + ((size_t)(b << 12) + tc) * PCOLS;

            float ep = 0.0f;
            #pragma unroll
            for (int q = 0; q < 2; q++) {
                int f = lane + 32 * q;
                float4 ps = *reinterpret_cast<const float4*>(Ps + 4 * f);
                float4 pt = *reinterpret_cast<const float4*>(Pt + 256 + 4 * f);
                float4 bb = *reinterpret_cast<const float4*>(b1s + 4 * f);
                float4 ww = *reinterpret_cast<const float4*>(W2s + 4 * f);
                ep += fmaxf(ps.x + pt.x + bb.x, 0.0f) * ww.x;
                ep += fmaxf(ps.y + pt.y + bb.y, 0.0f) * ww.y;
                ep += fmaxf(ps.z + pt.z + bb.z, 0.0f) * ww.z;
                ep += fmaxf(ps.w + pt.w + bb.w, 0.0f) * ww.w;
            }
            #pragma unroll
            for (int o = 16; o; o >>= 1) ep += __shfl_xor_sync(0xffffffffu, ep, o);

            {
                float4 ps = *reinterpret_cast<const float4*>(Ps + 512 + 4 * lane);
                float4 pt = *reinterpret_cast<const float4*>(Pt + 640 + 4 * lane);
                float4 aa = *reinterpret_cast<const float4*>(a1s + 4 * lane);
                float g0 = fmaxf(ps.x + pt.x + aa.x, 0.0f);
                float g1 = fmaxf(ps.y + pt.y + aa.y, 0.0f);
                float g2 = fmaxf(ps.z + pt.z + aa.z, 0.0f);
                float g3 = fmaxf(ps.w + pt.w + aa.w, 0.0f);
                float h0 = __bfloat162float(__float2bfloat16_rn(g0));
                float h1 = __bfloat162float(__float2bfloat16_rn(g1));
                float h2 = __bfloat162float(__float2bfloat16_rn(g2));
                float h3 = __bfloat162float(__float2bfloat16_rn(g3));
                const uint32_t sw = 4u * (e & 7);
                const uint32_t o0 = (uint32_t)(e * 64) + ((2u * lane)     ^ sw);
                const uint32_t o1 = (uint32_t)(e * 64) + ((2u * lane + 1) ^ sw);
                stg_h[w][o0] = pack_bf16(h0, h1);
                stg_h[w][o1] = pack_bf16(h2, h3);
                stg_l[w][o0] = pack_bf16(g0 - h0, g1 - h1);
                stg_l[w][o1] = pack_bf16(g2 - h2, g3 - h3);
            }

            const float srcA = army[(b << 12) + sc];
            const float tgtA = army[(b << 12) + tc];
            if (lane == 0) {
                float el = ep + b2v;
                bool valid = (src >= 0) && (tgt >= 0);
                if (valid && ((srcA <= 2.0f) || (tgtA >= 3.0f * srcA))) el -= 1.0f;
                if (valid && (src == tgt))                              el -= 100.0f;
                out_edge[eidx] = el;
                srcAs[w][e] = srcA;
            }
        }
        __syncwarp();

        // ---- phase 2: [16,128] @ [128,64] via mma, 3-term bf16 ----
        float acc[8][4];
        #pragma unroll
        for (int nj = 0; nj < 8; nj++)
            #pragma unroll
            for (int q = 0; q < 4; q++) acc[nj][q] = 0.0f;

        const uint32_t swg = 4u * grp;
        #pragma unroll
        for (int ks = 0; ks < 8; ks++) {
            const uint32_t kb = 8u * ks;
            uint32_t ah0 = stg_h[w][grp * 64       + ((kb + tig)     ^ swg)];
            uint32_t ah1 = stg_h[w][(grp + 8) * 64 + ((kb + tig)     ^ swg)];
            uint32_t ah2 = stg_h[w][grp * 64       + ((kb + 4 + tig) ^ swg)];
            uint32_t ah3 = stg_h[w][(grp + 8) * 64 + ((kb + 4 + tig) ^ swg)];
            uint32_t al0 = stg_l[w][grp * 64       + ((kb + tig)     ^ swg)];
            uint32_t al1 = stg_l[w][(grp + 8) * 64 + ((kb + tig)     ^ swg)];
            uint32_t al2 = stg_l[w][grp * 64       + ((kb + 4 + tig) ^ swg)];
            uint32_t al3 = stg_l[w][(grp + 8) * 64 + ((kb + 4 + tig) ^ swg)];
            #pragma unroll
            for (int nj = 0; nj < 8; nj++) {
                const int bi = (nj * 8 + grp) * 64 + kb + tig;
                uint32_t bh0 = g_A2Th[bi], bh1 = g_A2Th[bi + 4];
                uint32_t bl0 = g_A2Tl[bi], bl1 = g_A2Tl[bi + 4];
                mma_bf16(acc[nj], ah0, ah1, ah2, ah3, bh0, bh1);
                mma_bf16(acc[nj], ah0, ah1, ah2, ah3, bl0, bl1);
                mma_bf16(acc[nj], al0, al1, al2, al3, bh0, bh1);
            }
        }

        const float mS0 = srcAs[w][grp] - 1.0f;
        const float mS1 = srcAs[w][grp + 8] - 1.0f;
        float* o0 = out_army + (size_t)(e0 + grp) * 64;
        float* o1 = out_army + (size_t)(e0 + grp + 8) * 64;
        #pragma unroll
        for (int nj = 0; nj < 8; nj++) {
            const int m = nj * 8 + 2 * tig;
            const float fm0 = (float)m, fm1 = (float)(m + 1);
            float v0 = (fm0 <= mS0) ? acc[nj][0] + a2g[nj].x : -1e9f;
            float v1 = (fm1 <= mS0) ? acc[nj][1] + a2g[nj].y : -1e9f;
            float v2 = (fm0 <= mS1) ? acc[nj][2] + a2g[nj].x : -1e9f;
            float v3 = (fm1 <= mS1) ? acc[nj][3] + a2g[nj].y : -1e9f;
            *reinterpret_cast<float2*>(o0 + m) = make_float2(v0, v1);
            *reinterpret_cast<float2*>(o1 + m) = make_float2(v2, v3);
        }
        __syncwarp();
    }
}

// ---------------------------------------------------------------------------
// Launch
// ---------------------------------------------------------------------------
extern "C" void kernel_launch(void* const* d_in, const int* in_sizes, int n_in,
                              void* d_out, int out_size) {
    int i_node = -1, i_army = -1, i_edges = -1, i_W1 = -1, i_b1 = -1, i_W2 = -1,
        i_b2 = -1, i_A1 = -1, i_a1 = -1, i_A2 = -1, i_a2 = -1;
    for (int i = 0; i < n_in; i++) {
        switch (in_sizes[i]) {
            case 67108864: i_node = i; break;
            case 262144:   i_army = i; break;
            case 1048576:  i_edges = i; break;
            case 131072:   i_W1 = i; break;
            case 65536:    i_A1 = i; break;
            case 8192:     i_A2 = i; break;
            case 128:      i_a1 = i; break;
            case 64:       i_a2 = i; break;
            case 1:        i_b2 = i; break;
            case 256:      if (i_b1 < 0) i_b1 = i; else i_W2 = i; break;
            default: break;
        }
    }

    const float* node  = (const float*)d_in[i_node];
    const float* army  = (const float*)d_in[i_army];
    const int*   edges = (const int*)  d_in[i_edges];

    float* out_edge = (float*)d_out;
    float* out_army = (float*)d_out + NEDGE;

    // idempotent host-side attribute set (not a stream op; capture-safe)
    cudaFuncSetAttribute(gemm_kernel, cudaFuncAttributeMaxDynamicSharedMemorySize, GEMM_SMEM);

    prep_a_kernel<<<(MROWS * 64 + 255) / 256, 256>>>(node);
    prep_w_kernel<<<(PCOLS * K3 + 255) / 256, 256>>>((const float*)d_in[i_W1],
                                                     (const float*)d_in[i_A1]);
    prep_a2_kernel<<<16, 256>>>((const float*)d_in[i_A2]);

    dim3 ggrid(PCOLS / 128, MROWS / 128);            // (6, 2048)
    gemm_kernel<<<ggrid, 256, GEMM_SMEM>>>();

    edge_kernel<<<EDGE_GRID, 128>>>(army, edges,
                                    (const float*)d_in[i_b1], (const float*)d_in[i_W2],
                                    (const float*)d_in[i_b2], (const float*)d_in[i_a1],
                                    (const float*)d_in[i_a2],
                                    out_edge, out_army);
}

// round 10
// speedup vs baseline: 3.0288x; 1.2268x over previous
#include <cuda_runtime.h>
#include <cuda_bf16.h>
#include <cuda_fp16.h>
#include <cstdint>

// ---------------- problem constants ----------------
#define Bsz 64
#define Nn  4096
#define Ee  8192
#define MROWS (Bsz * Nn)        // 262144
#define PCOLS 768               // [W1top(256) | W1bot(256) | A1top(128) | A1bot(128)]
#define KDIM  256
#define NEDGE (Bsz * Ee)        // 524288

// ---------------- scratch (__device__ globals; no allocs allowed) ----------
__device__ __align__(16) float    g_P[(size_t)MROWS * PCOLS];   // partials (805 MB)
__device__ __align__(16) __half   g_Ahf[(size_t)MROWS * 512];   // [m][0:256)=hi, [256:512)=lo (fp16)
__device__ __align__(16) __half   g_B2[(size_t)PCOLS * 256];    // [n][k] = fp16(Wcat[k][n])
__device__ __align__(16) uint32_t g_A2Th[64 * 64];              // A2^T hi (bf16 pairs)
__device__ __align__(16) uint32_t g_A2Tl[64 * 64];              // A2^T lo

// ---------------- helpers ----------------
__device__ __forceinline__ uint32_t smem_u32(const void* p) {
    uint32_t a;
    asm("{ .reg .u64 t; cvta.to.shared.u64 t, %1; cvt.u32.u64 %0, t; }" : "=r"(a) : "l"(p));
    return a;
}
__device__ __forceinline__ void cp16(uint32_t dst, const void* src) {
    asm volatile("cp.async.cg.shared.global [%0], [%1], 16;" :: "r"(dst), "l"(src));
}
#define CP_COMMIT() asm volatile("cp.async.commit_group;" ::: "memory")
#define CP_WAIT(n)  asm volatile("cp.async.wait_group %0;" :: "n"(n) : "memory")

__device__ __forceinline__ void mma_f16(float* c,
    uint32_t a0, uint32_t a1, uint32_t a2, uint32_t a3, uint32_t b0, uint32_t b1) {
    asm volatile(
        "mma.sync.aligned.m16n8k16.row.col.f32.f16.f16.f32 "
        "{%0,%1,%2,%3}, {%4,%5,%6,%7}, {%8,%9}, {%0,%1,%2,%3};"
        : "+f"(c[0]), "+f"(c[1]), "+f"(c[2]), "+f"(c[3])
        : "r"(a0), "r"(a1), "r"(a2), "r"(a3), "r"(b0), "r"(b1));
}
__device__ __forceinline__ void mma_bf16(float* c,
    uint32_t a0, uint32_t a1, uint32_t a2, uint32_t a3, uint32_t b0, uint32_t b1) {
    asm volatile(
        "mma.sync.aligned.m16n8k16.row.col.f32.bf16.bf16.f32 "
        "{%0,%1,%2,%3}, {%4,%5,%6,%7}, {%8,%9}, {%0,%1,%2,%3};"
        : "+f"(c[0]), "+f"(c[1]), "+f"(c[2]), "+f"(c[3])
        : "r"(a0), "r"(a1), "r"(a2), "r"(a3), "r"(b0), "r"(b1));
}
__device__ __forceinline__ void ldsm_x4(uint32_t* r, uint32_t addr) {
    asm volatile("ldmatrix.sync.aligned.m8n8.x4.shared.b16 {%0,%1,%2,%3}, [%4];"
        : "=r"(r[0]), "=r"(r[1]), "=r"(r[2]), "=r"(r[3]) : "r"(addr));
}
__device__ __forceinline__ void ldsm_x2(uint32_t* r, uint32_t addr) {
    asm volatile("ldmatrix.sync.aligned.m8n8.x2.shared.b16 {%0,%1}, [%2];"
        : "=r"(r[0]), "=r"(r[1]) : "r"(addr));
}
__device__ __forceinline__ uint32_t pack_bf16(float lo, float hi) {
    __nv_bfloat162 t = __floats2bfloat162_rn(lo, hi);
    return *reinterpret_cast<uint32_t*>(&t);
}

// ---------------------------------------------------------------------------
// prep_a: split node embeddings into fp16 hi/lo (exact: A = Ah + Al to fp16x2).
// ---------------------------------------------------------------------------
__global__ __launch_bounds__(256) void prep_a_kernel(const float* __restrict__ node) {
    int i = blockIdx.x * blockDim.x + threadIdx.x;
    if (i >= MROWS * 64) return;
    int m  = i >> 6;
    int kq = (i & 63) * 4;
    float4 v = *reinterpret_cast<const float4*>(node + (size_t)m * 256 + kq);
    __half h[4], l[4];
    float vv[4] = {v.x, v.y, v.z, v.w};
    #pragma unroll
    for (int j = 0; j < 4; j++) {
        h[j] = __float2half_rn(vv[j]);
        l[j] = __float2half_rn(vv[j] - __half2float(h[j]));
    }
    *reinterpret_cast<uint2*>(&g_Ahf[(size_t)m * 512 + kq])       = *reinterpret_cast<uint2*>(h);
    *reinterpret_cast<uint2*>(&g_Ahf[(size_t)m * 512 + 256 + kq]) = *reinterpret_cast<uint2*>(l);
}

// ---------------------------------------------------------------------------
// prep_w: g_B2[n][k] = fp16(Wcat[k][n])
// ---------------------------------------------------------------------------
__global__ __launch_bounds__(256) void prep_w_kernel(const float* __restrict__ W1,
                                                     const float* __restrict__ A1) {
    int i = blockIdx.x * blockDim.x + threadIdx.x;
    if (i >= PCOLS * 256) return;
    int n = i >> 8;
    int k = i & 255;
    float v;
    if (n < 256)        v = W1[k * 256 + n];
    else if (n < 512)   v = W1[(256 + k) * 256 + (n - 256)];
    else if (n < 640)   v = A1[k * 128 + (n - 512)];
    else                v = A1[(256 + k) * 128 + (n - 640)];
    g_B2[i] = __float2half_rn(v);
}

// ---------------------------------------------------------------------------
// prep_a2: A2^T hi/lo bf16 u32-packed fragments (edge matvec).
// ---------------------------------------------------------------------------
__global__ __launch_bounds__(256) void prep_a2_kernel(const float* __restrict__ A2) {
    int i = blockIdx.x * blockDim.x + threadIdx.x;
    if (i >= 64 * 64) return;
    int n  = i >> 6;
    int kk = i & 63;
    float v0 = A2[(2 * kk)     * 64 + n];
    float v1 = A2[(2 * kk + 1) * 64 + n];
    float h0 = __bfloat162float(__float2bfloat16_rn(v0));
    float h1 = __bfloat162float(__float2bfloat16_rn(v1));
    g_A2Th[i] = pack_bf16(h0, h1);
    g_A2Tl[i] = pack_bf16(v0 - h0, v1 - h1);
}

// ---------------------------------------------------------------------------
// GEMM: g_P[262144,768] = [Ah|Al] @ [Bh;Bh] (fp16 2-term, f32 acc), K2 = 512.
// 128x128 tile, BK=32, 16 iters, 3-stage cp.async pipeline, 1 sync/iter,
// ldmatrix fragments, 2 CTAs/SM. Both K-segments read the SAME Bh slice.
// ---------------------------------------------------------------------------
#define BK 32
#define AST 40                    // smem row stride in halves
#define STG_H (128 * AST)         // halves per array per stage
#define STAGE_B (2 * STG_H * 2)   // bytes per stage (A+B)
#define GEMM_SMEM (3 * STAGE_B)   // 61440
#define KITERS 16

__global__ __launch_bounds__(256, 2) void gemm_kernel() {
    extern __shared__ __align__(16) __half dyn[];
    const uint32_t sb = smem_u32(dyn);

    const int tid  = threadIdx.x;
    const int wid  = tid >> 5, lane = tid & 31;
    const int g    = lane >> 2, tig = lane & 3;
    const int warp_m = (wid >> 2) * 64;
    const int warp_n = (wid & 3) * 32;
    const int n0 = blockIdx.x * 128;
    const int m0 = blockIdx.y * 128;

    float acc[4][4][4];
    #pragma unroll
    for (int i = 0; i < 4; i++)
        #pragma unroll
        for (int j = 0; j < 4; j++)
            #pragma unroll
            for (int q = 0; q < 4; q++) acc[i][j][q] = 0.0f;

    auto load_stage = [&](int ks, int buf) {
        const int seg  = ks >> 3;                       // 0: Ah, 1: Al
        const int a_k0 = seg * 256 + (ks & 7) * BK;
        const int b_k0 = (ks & 7) * BK;                 // Bh reused across segments
        const uint32_t da = sb + (uint32_t)buf * STAGE_B;
        const uint32_t db = da + STG_H * 2;
        #pragma unroll
        for (int h = 0; h < 2; h++) {
            int id = tid + h * 256;
            int r  = id >> 2, p = id & 3;
            cp16(da + (uint32_t)(r * AST + p * 8) * 2,
                 &g_Ahf[(size_t)(m0 + r) * 512 + a_k0 + p * 8]);
            cp16(db + (uint32_t)(r * AST + p * 8) * 2,
                 &g_B2[(size_t)(n0 + r) * 256 + b_k0 + p * 8]);
        }
    };

    const int a_row = lane & 15;
    const int a_k8  = ((lane >> 4) & 1) * 8;
    const int b_row = lane & 7;
    const int b_k8  = ((lane >> 3) & 1) * 8;

    load_stage(0, 0); CP_COMMIT();
    load_stage(1, 1); CP_COMMIT();

    for (int ks = 0; ks < KITERS; ks++) {
        if (ks < KITERS - 2) { CP_WAIT(1); } else { CP_WAIT(0); }
        __syncthreads();

        const uint32_t aB = sb + (uint32_t)(ks % 3) * STAGE_B;
        const uint32_t bB = aB + STG_H * 2;

        #pragma unroll
        for (int ksel = 0; ksel < 2; ksel++) {
            uint32_t a[4][4], b[4][2];
            #pragma unroll
            for (int mi = 0; mi < 4; mi++) {
                int row = warp_m + mi * 16 + a_row;
                ldsm_x4(a[mi], aB + (uint32_t)(row * AST + ksel * 16 + a_k8) * 2);
            }
            #pragma unroll
            for (int nj = 0; nj < 4; nj++) {
                int row = warp_n + nj * 8 + b_row;
                ldsm_x2(b[nj], bB + (uint32_t)(row * AST + ksel * 16 + b_k8) * 2);
            }
            #pragma unroll
            for (int mi = 0; mi < 4; mi++)
                #pragma unroll
                for (int nj = 0; nj < 4; nj++)
                    mma_f16(acc[mi][nj], a[mi][0], a[mi][1], a[mi][2], a[mi][3],
                            b[nj][0], b[nj][1]);
        }

        if (ks + 2 < KITERS) { load_stage(ks + 2, (ks + 2) % 3); CP_COMMIT(); }
    }

    #pragma unroll
    for (int mi = 0; mi < 4; mi++) {
        #pragma unroll
        for (int nj = 0; nj < 4; nj++) {
            int row = m0 + warp_m + mi * 16 + g;
            int col = n0 + warp_n + nj * 8 + 2 * tig;
            *reinterpret_cast<float2*>(&g_P[(size_t)row * PCOLS + col]) =
                make_float2(acc[mi][nj][0], acc[mi][nj][1]);
            *reinterpret_cast<float2*>(&g_P[(size_t)(row + 8) * PCOLS + col]) =
                make_float2(acc[mi][nj][2], acc[mi][nj][3]);
        }
    }
}

// ---------------------------------------------------------------------------
// Edge kernel: warp-batched (16 edges/tile), small grid for L2-resident gather.
// ---------------------------------------------------------------------------
#define EW 4
#define NTILES (NEDGE / 16)      // 32768
#define EDGE_GRID 592

__global__ __launch_bounds__(128) void edge_kernel(
    const float* __restrict__ army, const int* __restrict__ edges,
    const float* __restrict__ b1, const float* __restrict__ W2, const float* __restrict__ b2,
    const float* __restrict__ a1, const float* __restrict__ a2,
    float* __restrict__ out_edge, float* __restrict__ out_army)
{
    __shared__ uint32_t stg_h[EW][16 * 64];
    __shared__ uint32_t stg_l[EW][16 * 64];
    __shared__ float b1s[256], W2s[256], a1s[128];
    __shared__ float srcAs[EW][16];

    const int tid = threadIdx.x, w = tid >> 5, lane = tid & 31;
    const int grp = lane >> 2, tig = lane & 3;

    b1s[tid] = b1[tid];       b1s[tid + 128] = b1[tid + 128];
    W2s[tid] = W2[tid];       W2s[tid + 128] = W2[tid + 128];
    a1s[tid] = a1[tid];
    const float b2v = b2[0];

    float2 a2g[8];
    #pragma unroll
    for (int nj = 0; nj < 8; nj++) {
        int m = nj * 8 + 2 * tig;
        a2g[nj] = make_float2(a2[m], a2[m + 1]);
    }
    __syncthreads();

    for (int tile = blockIdx.x * EW + w; tile < NTILES; tile += EDGE_GRID * EW) {
        const int e0 = tile * 16;

        #pragma unroll 2
        for (int e = 0; e < 16; e++) {
            const int eidx = e0 + e;
            const int b = eidx >> 13;
            const int src = edges[2 * eidx], tgt = edges[2 * eidx + 1];
            const int sc = min(max(src, 0), Nn - 1);
            const int tc = min(max(tgt, 0), Nn - 1);
            const float* Ps = g_P + ((size_t)(b << 12) + sc) * PCOLS;
            const float* Pt = g_P + ((size_t)(b << 12) + tc) * PCOLS;

            float ep = 0.0f;
            #pragma unroll
            for (int q = 0; q < 2; q++) {
                int f = lane + 32 * q;
                float4 ps = *reinterpret_cast<const float4*>(Ps + 4 * f);
                float4 pt = *reinterpret_cast<const float4*>(Pt + 256 + 4 * f);
                float4 bb = *reinterpret_cast<const float4*>(b1s + 4 * f);
                float4 ww = *reinterpret_cast<const float4*>(W2s + 4 * f);
                ep += fmaxf(ps.x + pt.x + bb.x, 0.0f) * ww.x;
                ep += fmaxf(ps.y + pt.y + bb.y, 0.0f) * ww.y;
                ep += fmaxf(ps.z + pt.z + bb.z, 0.0f) * ww.z;
                ep += fmaxf(ps.w + pt.w + bb.w, 0.0f) * ww.w;
            }
            #pragma unroll
            for (int o = 16; o; o >>= 1) ep += __shfl_xor_sync(0xffffffffu, ep, o);

            {
                float4 ps = *reinterpret_cast<const float4*>(Ps + 512 + 4 * lane);
                float4 pt = *reinterpret_cast<const float4*>(Pt + 640 + 4 * lane);
                float4 aa = *reinterpret_cast<const float4*>(a1s + 4 * lane);
                float g0 = fmaxf(ps.x + pt.x + aa.x, 0.0f);
                float g1 = fmaxf(ps.y + pt.y + aa.y, 0.0f);
                float g2 = fmaxf(ps.z + pt.z + aa.z, 0.0f);
                float g3 = fmaxf(ps.w + pt.w + aa.w, 0.0f);
                float h0 = __bfloat162float(__float2bfloat16_rn(g0));
                float h1 = __bfloat162float(__float2bfloat16_rn(g1));
                float h2 = __bfloat162float(__float2bfloat16_rn(g2));
                float h3 = __bfloat162float(__float2bfloat16_rn(g3));
                const uint32_t sw = 4u * (e & 7);
                const uint32_t o0 = (uint32_t)(e * 64) + ((2u * lane)     ^ sw);
                const uint32_t o1 = (uint32_t)(e * 64) + ((2u * lane + 1) ^ sw);
                stg_h[w][o0] = pack_bf16(h0, h1);
                stg_h[w][o1] = pack_bf16(h2, h3);
                stg_l[w][o0] = pack_bf16(g0 - h0, g1 - h1);
                stg_l[w][o1] = pack_bf16(g2 - h2, g3 - h3);
            }

            const float srcA = army[(b << 12) + sc];
            const float tgtA = army[(b << 12) + tc];
            if (lane == 0) {
                float el = ep + b2v;
                bool valid = (src >= 0) && (tgt >= 0);
                if (valid && ((srcA <= 2.0f) || (tgtA >= 3.0f * srcA))) el -= 1.0f;
                if (valid && (src == tgt))                              el -= 100.0f;
                out_edge[eidx] = el;
                srcAs[w][e] = srcA;
            }
        }
        __syncwarp();

        float acc[8][4];
        #pragma unroll
        for (int nj = 0; nj < 8; nj++)
            #pragma unroll
            for (int q = 0; q < 4; q++) acc[nj][q] = 0.0f;

        const uint32_t swg = 4u * grp;
        #pragma unroll
        for (int ks = 0; ks < 8; ks++) {
            const uint32_t kb = 8u * ks;
            uint32_t ah0 = stg_h[w][grp * 64       + ((kb + tig)     ^ swg)];
            uint32_t ah1 = stg_h[w][(grp + 8) * 64 + ((kb + tig)     ^ swg)];
            uint32_t ah2 = stg_h[w][grp * 64       + ((kb + 4 + tig) ^ swg)];
            uint32_t ah3 = stg_h[w][(grp + 8) * 64 + ((kb + 4 + tig) ^ swg)];
            uint32_t al0 = stg_l[w][grp * 64       + ((kb + tig)     ^ swg)];
            uint32_t al1 = stg_l[w][(grp + 8) * 64 + ((kb + tig)     ^ swg)];
            uint32_t al2 = stg_l[w][grp * 64       + ((kb + 4 + tig) ^ swg)];
            uint32_t al3 = stg_l[w][(grp + 8) * 64 + ((kb + 4 + tig) ^ swg)];
            #pragma unroll
            for (int nj = 0; nj < 8; nj++) {
                const int bi = (nj * 8 + grp) * 64 + kb + tig;
                uint32_t bh0 = g_A2Th[bi], bh1 = g_A2Th[bi + 4];
                uint32_t bl0 = g_A2Tl[bi], bl1 = g_A2Tl[bi + 4];
                mma_bf16(acc[nj], ah0, ah1, ah2, ah3, bh0, bh1);
                mma_bf16(acc[nj], ah0, ah1, ah2, ah3, bl0, bl1);
                mma_bf16(acc[nj], al0, al1, al2, al3, bh0, bh1);
            }
        }

        const float mS0 = srcAs[w][grp] - 1.0f;
        const float mS1 = srcAs[w][grp + 8] - 1.0f;
        float* o0 = out_army + (size_t)(e0 + grp) * 64;
        float* o1 = out_army + (size_t)(e0 + grp + 8) * 64;
        #pragma unroll
        for (int nj = 0; nj < 8; nj++) {
            const int m = nj * 8 + 2 * tig;
            const float fm0 = (float)m, fm1 = (float)(m + 1);
            float v0 = (fm0 <= mS0) ? acc[nj][0] + a2g[nj].x : -1e9f;
            float v1 = (fm1 <= mS0) ? acc[nj][1] + a2g[nj].y : -1e9f;
            float v2 = (fm0 <= mS1) ? acc[nj][2] + a2g[nj].x : -1e9f;
            float v3 = (fm1 <= mS1) ? acc[nj][3] + a2g[nj].y : -1e9f;
            *reinterpret_cast<float2*>(o0 + m) = make_float2(v0, v1);
            *reinterpret_cast<float2*>(o1 + m) = make_float2(v2, v3);
        }
        __syncwarp();
    }
}

// ---------------------------------------------------------------------------
// Launch
// ---------------------------------------------------------------------------
extern "C" void kernel_launch(void* const* d_in, const int* in_sizes, int n_in,
                              void* d_out, int out_size) {
    int i_node = -1, i_army = -1, i_edges = -1, i_W1 = -1, i_b1 = -1, i_W2 = -1,
        i_b2 = -1, i_A1 = -1, i_a1 = -1, i_A2 = -1, i_a2 = -1;
    for (int i = 0; i < n_in; i++) {
        switch (in_sizes[i]) {
            case 67108864: i_node = i; break;
            case 262144:   i_army = i; break;
            case 1048576:  i_edges = i; break;
            case 131072:   i_W1 = i; break;
            case 65536:    i_A1 = i; break;
            case 8192:     i_A2 = i; break;
            case 128:      i_a1 = i; break;
            case 64:       i_a2 = i; break;
            case 1:        i_b2 = i; break;
            case 256:      if (i_b1 < 0) i_b1 = i; else i_W2 = i; break;
            default: break;
        }
    }

    const float* node  = (const float*)d_in[i_node];
    const float* army  = (const float*)d_in[i_army];
    const int*   edges = (const int*)  d_in[i_edges];

    float* out_edge = (float*)d_out;
    float* out_army = (float*)d_out + NEDGE;

    cudaFuncSetAttribute(gemm_kernel, cudaFuncAttributeMaxDynamicSharedMemorySize, GEMM_SMEM);

    prep_a_kernel<<<(MROWS * 64 + 255) / 256, 256>>>(node);
    prep_w_kernel<<<(PCOLS * 256 + 255) / 256, 256>>>((const float*)d_in[i_W1],
                                                      (const float*)d_in[i_A1]);
    prep_a2_kernel<<<16, 256>>>((const float*)d_in[i_A2]);

    dim3 ggrid(PCOLS / 128, MROWS / 128);            // (6, 2048)
    gemm_kernel<<<ggrid, 256, GEMM_SMEM>>>();

    edge_kernel<<<EDGE_GRID, 128>>>(army, edges,
                                    (const float*)d_in[i_b1], (const float*)d_in[i_W2],
                                    (const float*)d_in[i_b2], (const float*)d_in[i_a1],
                                    (const float*)d_in[i_a2],
                                    out_edge, out_army);
}

// round 11
// speedup vs baseline: 3.0840x; 1.0182x over previous
#include <cuda_runtime.h>
#include <cuda_bf16.h>
#include <cuda_fp16.h>
#include <cstdint>

// ---------------- problem constants ----------------
#define Bsz 64
#define Nn  4096
#define Ee  8192
#define MROWS (Bsz * Nn)        // 262144
#define PCOLS 768               // [W1top(256) | W1bot(256) | A1top(128) | A1bot(128)]
#define KDIM  256
#define NEDGE (Bsz * Ee)        // 524288

// ---------------- scratch (__device__ globals; no allocs allowed) ----------
__device__ __align__(16) float    g_P[(size_t)MROWS * PCOLS];   // partials (805 MB)
__device__ __align__(16) __half   g_Ahf[(size_t)MROWS * 512];   // [m][0:256)=hi, [256:512)=lo
__device__ __align__(16) __half   g_B2[(size_t)PCOLS * 256];    // [n][k] = fp16(Wcat[k][n])
__device__ __align__(16) uint32_t g_A2Th[64 * 64];              // A2^T hi (bf16 pairs)
__device__ __align__(16) uint32_t g_A2Tl[64 * 64];              // A2^T lo

// ---------------- helpers ----------------
__device__ __forceinline__ uint32_t smem_u32(const void* p) {
    uint32_t a;
    asm("{ .reg .u64 t; cvta.to.shared.u64 t, %1; cvt.u32.u64 %0, t; }" : "=r"(a) : "l"(p));
    return a;
}
__device__ __forceinline__ void cp16(uint32_t dst, const void* src) {
    asm volatile("cp.async.cg.shared.global [%0], [%1], 16;" :: "r"(dst), "l"(src));
}
#define CP_COMMIT() asm volatile("cp.async.commit_group;" ::: "memory")
#define CP_WAIT(n)  asm volatile("cp.async.wait_group %0;" :: "n"(n) : "memory")

__device__ __forceinline__ void mma_f16(float* c,
    uint32_t a0, uint32_t a1, uint32_t a2, uint32_t a3, uint32_t b0, uint32_t b1) {
    asm volatile(
        "mma.sync.aligned.m16n8k16.row.col.f32.f16.f16.f32 "
        "{%0,%1,%2,%3}, {%4,%5,%6,%7}, {%8,%9}, {%0,%1,%2,%3};"
        : "+f"(c[0]), "+f"(c[1]), "+f"(c[2]), "+f"(c[3])
        : "r"(a0), "r"(a1), "r"(a2), "r"(a3), "r"(b0), "r"(b1));
}
__device__ __forceinline__ void mma_bf16(float* c,
    uint32_t a0, uint32_t a1, uint32_t a2, uint32_t a3, uint32_t b0, uint32_t b1) {
    asm volatile(
        "mma.sync.aligned.m16n8k16.row.col.f32.bf16.bf16.f32 "
        "{%0,%1,%2,%3}, {%4,%5,%6,%7}, {%8,%9}, {%0,%1,%2,%3};"
        : "+f"(c[0]), "+f"(c[1]), "+f"(c[2]), "+f"(c[3])
        : "r"(a0), "r"(a1), "r"(a2), "r"(a3), "r"(b0), "r"(b1));
}
__device__ __forceinline__ void ldsm_x4(uint32_t* r, uint32_t addr) {
    asm volatile("ldmatrix.sync.aligned.m8n8.x4.shared.b16 {%0,%1,%2,%3}, [%4];"
        : "=r"(r[0]), "=r"(r[1]), "=r"(r[2]), "=r"(r[3]) : "r"(addr));
}
__device__ __forceinline__ void ldsm_x2(uint32_t* r, uint32_t addr) {
    asm volatile("ldmatrix.sync.aligned.m8n8.x2.shared.b16 {%0,%1}, [%2];"
        : "=r"(r[0]), "=r"(r[1]) : "r"(addr));
}
__device__ __forceinline__ uint32_t pack_bf16(float lo, float hi) {
    __nv_bfloat162 t = __floats2bfloat162_rn(lo, hi);
    return *reinterpret_cast<uint32_t*>(&t);
}

// ---------------------------------------------------------------------------
// prep_a: split node embeddings into fp16 hi/lo.
// ---------------------------------------------------------------------------
__global__ __launch_bounds__(256) void prep_a_kernel(const float* __restrict__ node) {
    int i = blockIdx.x * blockDim.x + threadIdx.x;
    if (i >= MROWS * 64) return;
    int m  = i >> 6;
    int kq = (i & 63) * 4;
    float4 v = *reinterpret_cast<const float4*>(node + (size_t)m * 256 + kq);
    __half h[4], l[4];
    float vv[4] = {v.x, v.y, v.z, v.w};
    #pragma unroll
    for (int j = 0; j < 4; j++) {
        h[j] = __float2half_rn(vv[j]);
        l[j] = __float2half_rn(vv[j] - __half2float(h[j]));
    }
    *reinterpret_cast<uint2*>(&g_Ahf[(size_t)m * 512 + kq])       = *reinterpret_cast<uint2*>(h);
    *reinterpret_cast<uint2*>(&g_Ahf[(size_t)m * 512 + 256 + kq]) = *reinterpret_cast<uint2*>(l);
}

// ---------------------------------------------------------------------------
// prep_w: g_B2[n][k] = fp16(Wcat[k][n])
// ---------------------------------------------------------------------------
__global__ __launch_bounds__(256) void prep_w_kernel(const float* __restrict__ W1,
                                                     const float* __restrict__ A1) {
    int i = blockIdx.x * blockDim.x + threadIdx.x;
    if (i >= PCOLS * 256) return;
    int n = i >> 8;
    int k = i & 255;
    float v;
    if (n < 256)        v = W1[k * 256 + n];
    else if (n < 512)   v = W1[(256 + k) * 256 + (n - 256)];
    else if (n < 640)   v = A1[k * 128 + (n - 512)];
    else                v = A1[(256 + k) * 128 + (n - 640)];
    g_B2[i] = __float2half_rn(v);
}

// ---------------------------------------------------------------------------
// prep_a2: A2^T hi/lo bf16 u32-packed fragments (edge matvec).
// ---------------------------------------------------------------------------
__global__ __launch_bounds__(256) void prep_a2_kernel(const float* __restrict__ A2) {
    int i = blockIdx.x * blockDim.x + threadIdx.x;
    if (i >= 64 * 64) return;
    int n  = i >> 6;
    int kk = i & 63;
    float v0 = A2[(2 * kk)     * 64 + n];
    float v1 = A2[(2 * kk + 1) * 64 + n];
    float h0 = __bfloat162float(__float2bfloat16_rn(v0));
    float h1 = __bfloat162float(__float2bfloat16_rn(v1));
    g_A2Th[i] = pack_bf16(h0, h1);
    g_A2Tl[i] = pack_bf16(v0 - h0, v1 - h1);
}

// ---------------------------------------------------------------------------
// GEMM: g_P[262144,768] = [Ah|Al] @ [Bh;Bh] (fp16 2-term, f32 acc), K2 = 512.
// 128x128 tile, BK=64 (8 iters), 3-stage cp.async pipeline, 1 sync/iter,
// ldmatrix fragments. 110.6KB smem/CTA, 2 CTAs/SM (221KB of 228KB).
// ---------------------------------------------------------------------------
#define BK 64
#define AST 72                    // smem row stride in halves (144B, ldsm conflict-free)
#define STG_H (128 * AST)         // halves per array per stage
#define STAGE_B (2 * STG_H * 2)   // bytes per stage (A+B) = 36864
#define GEMM_SMEM (3 * STAGE_B)   // 110592
#define KITERS 8

__global__ __launch_bounds__(256, 2) void gemm_kernel() {
    extern __shared__ __align__(16) __half dyn[];
    const uint32_t sb = smem_u32(dyn);

    const int tid  = threadIdx.x;
    const int wid  = tid >> 5, lane = tid & 31;
    const int g    = lane >> 2, tig = lane & 3;
    const int warp_m = (wid >> 2) * 64;
    const int warp_n = (wid & 3) * 32;
    const int n0 = blockIdx.x * 128;
    const int m0 = blockIdx.y * 128;

    float acc[4][4][4];
    #pragma unroll
    for (int i = 0; i < 4; i++)
        #pragma unroll
        for (int j = 0; j < 4; j++)
            #pragma unroll
            for (int q = 0; q < 4; q++) acc[i][j][q] = 0.0f;

    auto load_stage = [&](int ks, int buf) {
        const int seg  = ks >> 2;                       // 0: Ah, 1: Al
        const int a_k0 = seg * 256 + (ks & 3) * BK;
        const int b_k0 = (ks & 3) * BK;                 // Bh reused across segments
        const uint32_t da = sb + (uint32_t)buf * STAGE_B;
        const uint32_t db = da + STG_H * 2;
        #pragma unroll
        for (int h = 0; h < 4; h++) {
            int id = tid + h * 256;                     // 0..1023
            int r  = id >> 3, p = id & 7;
            cp16(da + (uint32_t)(r * AST + p * 8) * 2,
                 &g_Ahf[(size_t)(m0 + r) * 512 + a_k0 + p * 8]);
            cp16(db + (uint32_t)(r * AST + p * 8) * 2,
                 &g_B2[(size_t)(n0 + r) * 256 + b_k0 + p * 8]);
        }
    };

    const int a_row = lane & 15;
    const int a_k8  = ((lane >> 4) & 1) * 8;
    const int b_row = lane & 7;
    const int b_k8  = ((lane >> 3) & 1) * 8;

    load_stage(0, 0); CP_COMMIT();
    load_stage(1, 1); CP_COMMIT();

    for (int ks = 0; ks < KITERS; ks++) {
        if (ks < KITERS - 2) { CP_WAIT(1); } else { CP_WAIT(0); }
        __syncthreads();

        const uint32_t aB = sb + (uint32_t)(ks % 3) * STAGE_B;
        const uint32_t bB = aB + STG_H * 2;

        #pragma unroll
        for (int ksel = 0; ksel < 4; ksel++) {
            uint32_t a[4][4], b[4][2];
            #pragma unroll
            for (int mi = 0; mi < 4; mi++) {
                int row = warp_m + mi * 16 + a_row;
                ldsm_x4(a[mi], aB + (uint32_t)(row * AST + ksel * 16 + a_k8) * 2);
            }
            #pragma unroll
            for (int nj = 0; nj < 4; nj++) {
                int row = warp_n + nj * 8 + b_row;
                ldsm_x2(b[nj], bB + (uint32_t)(row * AST + ksel * 16 + b_k8) * 2);
            }
            #pragma unroll
            for (int mi = 0; mi < 4; mi++)
                #pragma unroll
                for (int nj = 0; nj < 4; nj++)
                    mma_f16(acc[mi][nj], a[mi][0], a[mi][1], a[mi][2], a[mi][3],
                            b[nj][0], b[nj][1]);
        }

        if (ks + 2 < KITERS) { load_stage(ks + 2, (ks + 2) % 3); CP_COMMIT(); }
    }

    #pragma unroll
    for (int mi = 0; mi < 4; mi++) {
        #pragma unroll
        for (int nj = 0; nj < 4; nj++) {
            int row = m0 + warp_m + mi * 16 + g;
            int col = n0 + warp_n + nj * 8 + 2 * tig;
            *reinterpret_cast<float2*>(&g_P[(size_t)row * PCOLS + col]) =
                make_float2(acc[mi][nj][0], acc[mi][nj][1]);
            *reinterpret_cast<float2*>(&g_P[(size_t)(row + 8) * PCOLS + col]) =
                make_float2(acc[mi][nj][2], acc[mi][nj][3]);
        }
    }
}

// ---------------------------------------------------------------------------
// Edge kernel: warp-batched (16 edges/tile). Grid doubled vs R9 for latency
// hiding; window ~116MB ~ L2 capacity.
// ---------------------------------------------------------------------------
#define EW 4
#define NTILES (NEDGE / 16)      // 32768
#define EDGE_GRID 1184

__global__ __launch_bounds__(128) void edge_kernel(
    const float* __restrict__ army, const int* __restrict__ edges,
    const float* __restrict__ b1, const float* __restrict__ W2, const float* __restrict__ b2,
    const float* __restrict__ a1, const float* __restrict__ a2,
    float* __restrict__ out_edge, float* __restrict__ out_army)
{
    __shared__ uint32_t stg_h[EW][16 * 64];
    __shared__ uint32_t stg_l[EW][16 * 64];
    __shared__ float b1s[256], W2s[256], a1s[128];
    __shared__ float srcAs[EW][16];

    const int tid = threadIdx.x, w = tid >> 5, lane = tid & 31;
    const int grp = lane >> 2, tig = lane & 3;

    b1s[tid] = b1[tid];       b1s[tid + 128] = b1[tid + 128];
    W2s[tid] = W2[tid];       W2s[tid + 128] = W2[tid + 128];
    a1s[tid] = a1[tid];
    const float b2v = b2[0];

    float2 a2g[8];
    #pragma unroll
    for (int nj = 0; nj < 8; nj++) {
        int m = nj * 8 + 2 * tig;
        a2g[nj] = make_float2(a2[m], a2[m + 1]);
    }
    __syncthreads();

    for (int tile = blockIdx.x * EW + w; tile < NTILES; tile += EDGE_GRID * EW) {
        const int e0 = tile * 16;

        #pragma unroll 2
        for (int e = 0; e < 16; e++) {
            const int eidx = e0 + e;
            const int b = eidx >> 13;
            const int src = edges[2 * eidx], tgt = edges[2 * eidx + 1];
            const int sc = min(max(src, 0), Nn - 1);
            const int tc = min(max(tgt, 0), Nn - 1);
            const float* Ps = g_P + ((size_t)(b << 12) + sc) * PCOLS;
            const float* Pt = g_P + ((size_t)(b << 12) + tc) * PCOLS;

            float ep = 0.0f;
            #pragma unroll
            for (int q = 0; q < 2; q++) {
                int f = lane + 32 * q;
                float4 ps = *reinterpret_cast<const float4*>(Ps + 4 * f);
                float4 pt = *reinterpret_cast<const float4*>(Pt + 256 + 4 * f);
                float4 bb = *reinterpret_cast<const float4*>(b1s + 4 * f);
                float4 ww = *reinterpret_cast<const float4*>(W2s + 4 * f);
                ep += fmaxf(ps.x + pt.x + bb.x, 0.0f) * ww.x;
                ep += fmaxf(ps.y + pt.y + bb.y, 0.0f) * ww.y;
                ep += fmaxf(ps.z + pt.z + bb.z, 0.0f) * ww.z;
                ep += fmaxf(ps.w + pt.w + bb.w, 0.0f) * ww.w;
            }
            #pragma unroll
            for (int o = 16; o; o >>= 1) ep += __shfl_xor_sync(0xffffffffu, ep, o);

            {
                float4 ps = *reinterpret_cast<const float4*>(Ps + 512 + 4 * lane);
                float4 pt = *reinterpret_cast<const float4*>(Pt + 640 + 4 * lane);
                float4 aa = *reinterpret_cast<const float4*>(a1s + 4 * lane);
                float g0 = fmaxf(ps.x + pt.x + aa.x, 0.0f);
                float g1 = fmaxf(ps.y + pt.y + aa.y, 0.0f);
                float g2 = fmaxf(ps.z + pt.z + aa.z, 0.0f);
                float g3 = fmaxf(ps.w + pt.w + aa.w, 0.0f);
                float h0 = __bfloat162float(__float2bfloat16_rn(g0));
                float h1 = __bfloat162float(__float2bfloat16_rn(g1));
                float h2 = __bfloat162float(__float2bfloat16_rn(g2));
                float h3 = __bfloat162float(__float2bfloat16_rn(g3));
                const uint32_t sw = 4u * (e & 7);
                const uint32_t o0 = (uint32_t)(e * 64) + ((2u * lane)     ^ sw);
                const uint32_t o1 = (uint32_t)(e * 64) + ((2u * lane + 1) ^ sw);
                stg_h[w][o0] = pack_bf16(h0, h1);
                stg_h[w][o1] = pack_bf16(h2, h3);
                stg_l[w][o0] = pack_bf16(g0 - h0, g1 - h1);
                stg_l[w][o1] = pack_bf16(g2 - h2, g3 - h3);
            }

            const float srcA = army[(b << 12) + sc];
            const float tgtA = army[(b << 12) + tc];
            if (lane == 0) {
                float el = ep + b2v;
                bool valid = (src >= 0) && (tgt >= 0);
                if (valid && ((srcA <= 2.0f) || (tgtA >= 3.0f * srcA))) el -= 1.0f;
                if (valid && (src == tgt))                              el -= 100.0f;
                out_edge[eidx] = el;
                srcAs[w][e] = srcA;
            }
        }
        __syncwarp();

        float acc[8][4];
        #pragma unroll
        for (int nj = 0; nj < 8; nj++)
            #pragma unroll
            for (int q = 0; q < 4; q++) acc[nj][q] = 0.0f;

        const uint32_t swg = 4u * grp;
        #pragma unroll
        for (int ks = 0; ks < 8; ks++) {
            const uint32_t kb = 8u * ks;
            uint32_t ah0 = stg_h[w][grp * 64       + ((kb + tig)     ^ swg)];
            uint32_t ah1 = stg_h[w][(grp + 8) * 64 + ((kb + tig)     ^ swg)];
            uint32_t ah2 = stg_h[w][grp * 64       + ((kb + 4 + tig) ^ swg)];
            uint32_t ah3 = stg_h[w][(grp + 8) * 64 + ((kb + 4 + tig) ^ swg)];
            uint32_t al0 = stg_l[w][grp * 64       + ((kb + tig)     ^ swg)];
            uint32_t al1 = stg_l[w][(grp + 8) * 64 + ((kb + tig)     ^ swg)];
            uint32_t al2 = stg_l[w][grp * 64       + ((kb + 4 + tig) ^ swg)];
            uint32_t al3 = stg_l[w][(grp + 8) * 64 + ((kb + 4 + tig) ^ swg)];
            #pragma unroll
            for (int nj = 0; nj < 8; nj++) {
                const int bi = (nj * 8 + grp) * 64 + kb + tig;
                uint32_t bh0 = g_A2Th[bi], bh1 = g_A2Th[bi + 4];
                uint32_t bl0 = g_A2Tl[bi], bl1 = g_A2Tl[bi + 4];
                mma_bf16(acc[nj], ah0, ah1, ah2, ah3, bh0, bh1);
                mma_bf16(acc[nj], ah0, ah1, ah2, ah3, bl0, bl1);
                mma_bf16(acc[nj], al0, al1, al2, al3, bh0, bh1);
            }
        }

        const float mS0 = srcAs[w][grp] - 1.0f;
        const float mS1 = srcAs[w][grp + 8] - 1.0f;
        float* o0 = out_army + (size_t)(e0 + grp) * 64;
        float* o1 = out_army + (size_t)(e0 + grp + 8) * 64;
        #pragma unroll
        for (int nj = 0; nj < 8; nj++) {
            const int m = nj * 8 + 2 * tig;
            const float fm0 = (float)m, fm1 = (float)(m + 1);
            float v0 = (fm0 <= mS0) ? acc[nj][0] + a2g[nj].x : -1e9f;
            float v1 = (fm1 <= mS0) ? acc[nj][1] + a2g[nj].y : -1e9f;
            float v2 = (fm0 <= mS1) ? acc[nj][2] + a2g[nj].x : -1e9f;
            float v3 = (fm1 <= mS1) ? acc[nj][3] + a2g[nj].y : -1e9f;
            *reinterpret_cast<float2*>(o0 + m) = make_float2(v0, v1);
            *reinterpret_cast<float2*>(o1 + m) = make_float2(v2, v3);
        }
        __syncwarp();
    }
}

// ---------------------------------------------------------------------------
// Launch
// ---------------------------------------------------------------------------
extern "C" void kernel_launch(void* const* d_in, const int* in_sizes, int n_in,
                              void* d_out, int out_size) {
    int i_node = -1, i_army = -1, i_edges = -1, i_W1 = -1, i_b1 = -1, i_W2 = -1,
        i_b2 = -1, i_A1 = -1, i_a1 = -1, i_A2 = -1, i_a2 = -1;
    for (int i = 0; i < n_in; i++) {
        switch (in_sizes[i]) {
            case 67108864: i_node = i; break;
            case 262144:   i_army = i; break;
            case 1048576:  i_edges = i; break;
            case 131072:   i_W1 = i; break;
            case 65536:    i_A1 = i; break;
            case 8192:     i_A2 = i; break;
            case 128:      i_a1 = i; break;
            case 64:       i_a2 = i; break;
            case 1:        i_b2 = i; break;
            case 256:      if (i_b1 < 0) i_b1 = i; else i_W2 = i; break;
            default: break;
        }
    }

    const float* node  = (const float*)d_in[i_node];
    const float* army  = (const float*)d_in[i_army];
    const int*   edges = (const int*)  d_in[i_edges];

    float* out_edge = (float*)d_out;
    float* out_army = (float*)d_out + NEDGE;

    cudaFuncSetAttribute(gemm_kernel, cudaFuncAttributeMaxDynamicSharedMemorySize, GEMM_SMEM);

    prep_a_kernel<<<(MROWS * 64 + 255) / 256, 256>>>(node);
    prep_w_kernel<<<(PCOLS * 256 + 255) / 256, 256>>>((const float*)d_in[i_W1],
                                                      (const float*)d_in[i_A1]);
    prep_a2_kernel<<<16, 256>>>((const float*)d_in[i_A2]);

    dim3 ggrid(PCOLS / 128, MROWS / 128);            // (6, 2048)
    gemm_kernel<<<ggrid, 256, GEMM_SMEM>>>();

    edge_kernel<<<EDGE_GRID, 128>>>(army, edges,
                                    (const float*)d_in[i_b1], (const float*)d_in[i_W2],
                                    (const float*)d_in[i_b2], (const float*)d_in[i_a1],
                                    (const float*)d_in[i_a2],
                                    out_edge, out_army);
}